// round 10
// baseline (speedup 1.0000x reference)
#include <cuda_runtime.h>
#include <cuda_bf16.h>
#include <cstdint>

#define Bb   4
#define Nn   2048
#define Ll   12
#define Dd   128
#define LD_  (Ll*Dd)      // 1536
#define MT   (Bb*Nn)      // 8192

typedef __nv_bfloat16 bf16;

// ---------------- scratch (device globals; no allocation) -------------------
__device__ bf16  g_h0h[MT * Dd];  __device__ bf16 g_h0l[MT * Dd];
__device__ bf16  g_h1h[MT * Dd];  __device__ bf16 g_h1l[MT * Dd];
__device__ bf16  g_aggh[MT * Dd]; __device__ bf16 g_aggl[MT * Dd];
__device__ bf16  g_hTh[Bb * Dd * Nn]; __device__ bf16 g_hTl[Bb * Dd * Nn];
__device__ bf16  g_adjh[Nn * Nn]; __device__ bf16 g_adjl[Nn * Nn];
__device__ bf16  g_xh [MT * LD_]; __device__ bf16 g_xl [MT * LD_];
__device__ bf16  g_W2h[Dd * LD_]; __device__ bf16 g_W2l[Dd * LD_];
__device__ bf16  g_W1h[LD_ * Dd]; __device__ bf16 g_W1l[LD_ * Dd];
__device__ bf16  g_Wrh[3][Dd * Dd]; __device__ bf16 g_Wrl[3][Dd * Dd];
__device__ bf16  g_Woh[3][Dd * Dd]; __device__ bf16 g_Wol[3][Dd * Dd];
__device__ float g_part[4][MT * Dd];   // split-K partials (16 MB)

// ---------------- helpers ----------------------------------------------------
__device__ __forceinline__ uint32_t smem_u32(const void* p) {
    uint32_t a;
    asm("{ .reg .u64 t; cvta.to.shared.u64 t, %1; cvt.u32.u64 %0, t; }"
        : "=r"(a) : "l"(p));
    return a;
}
__device__ __forceinline__ void cp_async16(uint32_t dst, const void* src) {
    asm volatile("cp.async.cg.shared.global [%0], [%1], 16;"
                 :: "r"(dst), "l"(src) : "memory");
}
__device__ __forceinline__ void cp_commit() {
    asm volatile("cp.async.commit_group;" ::: "memory");
}
template<int N_>
__device__ __forceinline__ void cp_wait() {
    asm volatile("cp.async.wait_group %0;" :: "n"(N_) : "memory");
}
__device__ __forceinline__ void ldmx4(uint32_t* r, uint32_t addr) {
    asm volatile("ldmatrix.sync.aligned.m8n8.x4.shared.b16 {%0,%1,%2,%3}, [%4];"
                 : "=r"(r[0]), "=r"(r[1]), "=r"(r[2]), "=r"(r[3]) : "r"(addr));
}
__device__ __forceinline__ void mma_bf16(float* c, const uint32_t* a, const uint32_t* b) {
    asm volatile(
        "mma.sync.aligned.m16n8k16.row.col.f32.bf16.bf16.f32 "
        "{%0,%1,%2,%3}, {%4,%5,%6,%7}, {%8,%9}, {%0,%1,%2,%3};"
        : "+f"(c[0]), "+f"(c[1]), "+f"(c[2]), "+f"(c[3])
        : "r"(a[0]), "r"(a[1]), "r"(a[2]), "r"(a[3]), "r"(b[0]), "r"(b[1]));
}
__device__ __forceinline__ void split2(float v, bf16& h, bf16& l) {
    h = __float2bfloat16(v);
    l = __float2bfloat16(v - __bfloat162float(h));
}

// ---------------- fused preprocessing ------------------------------------------
__global__ void adj_fused(const float* __restrict__ adj) {
    const int row = blockIdx.x;
    const int tid = threadIdx.x;
    const float* r = adj + (size_t)row * Nn;
    float v[8]; float s = 0.f;
    #pragma unroll
    for (int i = 0; i < 8; i++) { v[i] = r[tid + i * 256]; s += v[i]; }
    __shared__ float sm[8];
    #pragma unroll
    for (int o = 16; o > 0; o >>= 1) s += __shfl_down_sync(0xffffffffu, s, o);
    if ((tid & 31) == 0) sm[tid >> 5] = s;
    __syncthreads();
    __shared__ float rdeg;
    if (tid == 0) {
        float t = 0.f;
        #pragma unroll
        for (int i = 0; i < 8; i++) t += sm[i];
        rdeg = 1.0f / fmaxf(t, 1.0f);
    }
    __syncthreads();
    const float rd = rdeg;
    #pragma unroll
    for (int i = 0; i < 8; i++) {
        bf16 h, l;
        split2(v[i] * rd, h, l);
        size_t o = (size_t)row * Nn + tid + i * 256;
        g_adjh[o] = h; g_adjl[o] = l;
    }
}

__global__ void x_split_kernel(const float2* __restrict__ in) {
    int idx = blockIdx.x * blockDim.x + threadIdx.x;
    float2 v = in[idx];
    bf16 h0, l0, h1, l1;
    split2(v.x, h0, l0); split2(v.y, h1, l1);
    *reinterpret_cast<__nv_bfloat162*>(&g_xh[2 * idx]) = __nv_bfloat162(h0, h1);
    *reinterpret_cast<__nv_bfloat162*>(&g_xl[2 * idx]) = __nv_bfloat162(l0, l1);
}

__global__ void wtrans_all(const float* __restrict__ W2, const float* __restrict__ W1,
                           const float* __restrict__ Wr0, const float* __restrict__ Wo0,
                           const float* __restrict__ Wr1, const float* __restrict__ Wo1,
                           const float* __restrict__ Wr2, const float* __restrict__ Wo2)
{
    __shared__ float t[32][33];
    const int tb = blockIdx.x;
    const float* src; bf16* dh; bf16* dl; int R, C, tx, ty;
    if (tb < 192) {
        src = W2; dh = g_W2h; dl = g_W2l; R = LD_; C = Dd;
        ty = tb / 4; tx = tb % 4;
    } else if (tb < 384) {
        src = W1; dh = g_W1h; dl = g_W1l; R = Dd; C = LD_;
        int u = tb - 192; ty = u / 48; tx = u % 48;
    } else {
        int u = tb - 384; int l = u / 32; int v = u % 32;
        const float* wsrc[6] = {Wr0, Wo0, Wr1, Wo1, Wr2, Wo2};
        src = wsrc[l * 2 + (v < 16 ? 0 : 1)];
        if (v < 16) { dh = g_Wrh[l]; dl = g_Wrl[l]; }
        else        { dh = g_Woh[l]; dl = g_Wol[l]; }
        int w = v & 15; tx = w % 4; ty = w / 4; R = Dd; C = Dd;
    }
    const int c0 = tx * 32, r0 = ty * 32;
    const int x = threadIdx.x, y = threadIdx.y;
    #pragma unroll
    for (int i = 0; i < 32; i += 8)
        t[y + i][x] = src[(size_t)(r0 + y + i) * C + c0 + x];
    __syncthreads();
    #pragma unroll
    for (int i = 0; i < 32; i += 8) {
        bf16 h, l;
        split2(t[x][y + i], h, l);
        size_t o = (size_t)(c0 + y + i) * R + r0 + x;
        dh[o] = h; dl[o] = l;
    }
}

// ---------------- split-K reductions --------------------------------------------
template<bool BIAS, bool WT>
__global__ void reduce_k(const float2* __restrict__ p0, const float2* __restrict__ p1,
                         const float* __restrict__ bias,
                         bf16* __restrict__ Ch, bf16* __restrict__ Cl,
                         bf16* __restrict__ Th, bf16* __restrict__ Tl)
{
    const int idx = blockIdx.x * blockDim.x + threadIdx.x;   // over MT*Dd/2
    float2 a = p0[idx], b = p1[idx];
    float v0 = a.x + b.x, v1 = a.y + b.y;
    const int col = (2 * idx) & 127;
    if (BIAS) { v0 += bias[col]; v1 += bias[col + 1]; }
    bf16 h0, l0, h1, l1;
    split2(v0, h0, l0); split2(v1, h1, l1);
    *reinterpret_cast<__nv_bfloat162*>(Ch + 2 * idx) = __nv_bfloat162(h0, h1);
    *reinterpret_cast<__nv_bfloat162*>(Cl + 2 * idx) = __nv_bfloat162(l0, l1);
    if (WT) {
        const int row = (2 * idx) >> 7;
        const int bb_ = row >> 11, nn_ = row & 2047;
        const size_t ot = (size_t)bb_ * (Dd * (size_t)Nn) + (size_t)col * Nn + nn_;
        Th[ot] = h0;      Tl[ot] = l0;
        Th[ot + Nn] = h1; Tl[ot + Nn] = l1;
    }
}

__global__ void reduce_k4(const float2* __restrict__ p0, const float2* __restrict__ p1,
                          const float2* __restrict__ p2, const float2* __restrict__ p3,
                          bf16* __restrict__ Ch, bf16* __restrict__ Cl)
{
    const int idx = blockIdx.x * blockDim.x + threadIdx.x;   // over MT*Dd/2
    float2 a = p0[idx], b = p1[idx], c = p2[idx], d = p3[idx];
    float v0 = (a.x + b.x) + (c.x + d.x);
    float v1 = (a.y + b.y) + (c.y + d.y);
    bf16 h0, l0, h1, l1;
    split2(v0, h0, l0); split2(v1, h1, l1);
    *reinterpret_cast<__nv_bfloat162*>(Ch + 2 * idx) = __nv_bfloat162(h0, h1);
    *reinterpret_cast<__nv_bfloat162*>(Cl + 2 * idx) = __nv_bfloat162(l0, l1);
}

// ---------------- bf16x2 tensor-core GEMM -------------------------------------
// Identical to R9 except the k-tile body: ALL 16 ldmatrix are issued before
// ALL 24 MMAs (fragment double-buffering across the two k16 slices).
#define STAGES 3
#define BM 64
#define BN 128
#define BK 32
#define KS2 40
#define OFF_AL (64 * KS2)
#define OFF_BH (2 * 64 * KS2)
#define OFF_BL (OFF_BH + 128 * KS2)
#define STAGE_H (OFF_BL + 128 * KS2)
#define GEMM_SMEM (STAGES * STAGE_H * 2)    // 92160 B

template<bool DUAL, bool RELU, bool BIAS, bool WF32, bool WSPL, bool WT, bool SPLITK>
__global__ void __launch_bounds__(256, 2)
gemm_bf(const bf16* __restrict__ Ah, const bf16* __restrict__ Al,
        const bf16* __restrict__ Bh, const bf16* __restrict__ Bl,
        const bf16* __restrict__ A2h, const bf16* __restrict__ A2l,
        const bf16* __restrict__ B2h, const bf16* __restrict__ B2l,
        const float* __restrict__ bias,
        float* __restrict__ Cf, bf16* __restrict__ Ch, bf16* __restrict__ Cl,
        bf16* __restrict__ Th, bf16* __restrict__ Tl,
        int N, int ldK, int kLen, int zmask, int zshift,
        size_t sA, size_t sB, size_t sC, size_t sPart)
{
    extern __shared__ bf16 smem[];
    const uint32_t sbase = smem_u32(smem);
    const int tid = threadIdx.x;
    const int lane = tid & 31, wid = tid >> 5;
    const int warpM = wid & 1, warpN = wid >> 1;
    const int gid = lane >> 2, tg = lane & 3;

    const int m0 = blockIdx.y * BM, n0 = blockIdx.x * BN;
    int batch, split, kOff;
    if (SPLITK) { batch = blockIdx.z & zmask; split = blockIdx.z >> zshift;
                  kOff = split * kLen; }
    else        { batch = blockIdx.z; split = 0; kOff = 0; }

    const bf16* pAh = Ah + (size_t)batch * sA;
    const bf16* pAl = Al + (size_t)batch * sA;
    const bf16* pBh = Bh + (size_t)batch * sB;
    const bf16* pBl = Bl + (size_t)batch * sB;

    const int nk1 = kLen / BK;
    const int nk  = DUAL ? 2 * nk1 : nk1;

    auto issue = [&](int tile, int s) {
        const bf16 *ah, *al, *bh, *bl; int k0;
        if (DUAL && tile >= nk1) { ah = A2h; al = A2l; bh = B2h; bl = B2l;
                                   k0 = (tile - nk1) * BK; }
        else { ah = pAh; al = pAl; bh = pBh; bl = pBl; k0 = kOff + tile * BK; }
        const uint32_t st = sbase + s * (STAGE_H * 2);
        {
            int row = tid >> 2, c = tid & 3;
            uint32_t dof = (uint32_t)(row * KS2 + c * 8) * 2;
            size_t gof = (size_t)(m0 + row) * ldK + k0 + c * 8;
            cp_async16(st + dof,              ah + gof);
            cp_async16(st + OFF_AL * 2 + dof, al + gof);
        }
        #pragma unroll
        for (int i = 0; i < 2; i++) {
            int idx = tid + i * 256;
            int row = idx >> 2, c = idx & 3;
            uint32_t dof = (uint32_t)(row * KS2 + c * 8) * 2;
            size_t gof = (size_t)(n0 + row) * ldK + k0 + c * 8;
            cp_async16(st + OFF_BH * 2 + dof, bh + gof);
            cp_async16(st + OFF_BL * 2 + dof, bl + gof);
        }
        cp_commit();
    };

    float acc[2][4][4];
    #pragma unroll
    for (int mi = 0; mi < 2; mi++)
        #pragma unroll
        for (int ni = 0; ni < 4; ni++)
            #pragma unroll
            for (int j = 0; j < 4; j++) acc[mi][ni][j] = 0.f;

    const int ar = lane & 15, ak = (lane >> 4) * 8;
    const uint32_t a_off = (uint32_t)((warpM * 32 + ar) * KS2 + ak) * 2;
    const int nr = (lane & 7) + ((lane >> 4) * 8);
    const int bk = ((lane >> 3) & 1) * 8;
    const uint32_t b_off = (uint32_t)((warpN * 32 + nr) * KS2 + bk) * 2;

    #pragma unroll
    for (int s = 0; s < STAGES - 1; s++) issue(s, s);

    for (int kt = 0; kt < nk; ++kt) {
        cp_wait<STAGES - 2>();
        __syncthreads();
        if (kt + STAGES - 1 < nk) issue(kt + STAGES - 1, (kt + STAGES - 1) % STAGES);

        const uint32_t st = sbase + (kt % STAGES) * (STAGE_H * 2);
        const uint32_t aA = st + a_off;
        const uint32_t aB = st + OFF_BH * 2 + b_off;

        // ---- fragment double-buffer: ALL ldmatrix first, then ALL MMAs ----
        uint32_t fah[2][2][4], fal[2][2][4], fbh[2][2][4], fbl[2][2][4];
        #pragma unroll
        for (int ks = 0; ks < 2; ks++) {
            const uint32_t ko = ks * 32;
            #pragma unroll
            for (int mi = 0; mi < 2; mi++) {
                ldmx4(fah[ks][mi], aA + mi * (16 * KS2 * 2) + ko);
                ldmx4(fal[ks][mi], aA + OFF_AL * 2 + mi * (16 * KS2 * 2) + ko);
            }
            #pragma unroll
            for (int np = 0; np < 2; np++) {
                ldmx4(fbh[ks][np], aB + np * (16 * KS2 * 2) + ko);
                ldmx4(fbl[ks][np], aB + (OFF_BL - OFF_BH) * 2 + np * (16 * KS2 * 2) + ko);
            }
        }
        #pragma unroll
        for (int ks = 0; ks < 2; ks++)
            #pragma unroll
            for (int mi = 0; mi < 2; mi++)
                #pragma unroll
                for (int ni = 0; ni < 4; ni++) {
                    const int np = ni >> 1, jo = (ni & 1) * 2;
                    mma_bf16(acc[mi][ni], fah[ks][mi], &fbh[ks][np][jo]);
                    mma_bf16(acc[mi][ni], fah[ks][mi], &fbl[ks][np][jo]);
                    mma_bf16(acc[mi][ni], fal[ks][mi], &fbh[ks][np][jo]);
                }
    }
    cp_wait<0>();

    // epilogue
    const size_t obase = (SPLITK ? (size_t)split * sPart : 0) + (size_t)batch * sC;
    #pragma unroll
    for (int mi = 0; mi < 2; mi++) {
        const int rbase = m0 + warpM * 32 + mi * 16 + gid;
        #pragma unroll
        for (int ni = 0; ni < 4; ni++) {
            const int col = n0 + warpN * 32 + ni * 8 + 2 * tg;
            float* c = acc[mi][ni];
            float b0 = 0.f, b1 = 0.f;
            if (BIAS) { b0 = bias[col]; b1 = bias[col + 1]; }
            #pragma unroll
            for (int h2 = 0; h2 < 2; h2++) {
                const int row = rbase + 8 * h2;
                float v0 = c[2 * h2 + 0] + b0;
                float v1 = c[2 * h2 + 1] + b1;
                if (RELU) { v0 = fmaxf(v0, 0.f); v1 = fmaxf(v1, 0.f); }
                const size_t o = obase + (size_t)row * N + col;
                if (SPLITK || WF32)
                    *reinterpret_cast<float2*>(Cf + o) = make_float2(v0, v1);
                if (WSPL || WT) {
                    bf16 h0_, l0_, h1_, l1_;
                    split2(v0, h0_, l0_); split2(v1, h1_, l1_);
                    if (WSPL) {
                        *reinterpret_cast<__nv_bfloat162*>(Ch + o) = __nv_bfloat162(h0_, h1_);
                        *reinterpret_cast<__nv_bfloat162*>(Cl + o) = __nv_bfloat162(l0_, l1_);
                    }
                    if (WT) {
                        const int bb_ = row >> 11, nn_ = row & 2047;
                        const size_t ot = (size_t)bb_ * (Dd * (size_t)Nn)
                                        + (size_t)col * Nn + nn_;
                        Th[ot] = h0_;      Tl[ot] = l0_;
                        Th[ot + Nn] = h1_; Tl[ot + Nn] = l1_;
                    }
                }
            }
        }
    }
}

// ---------------- launch --------------------------------------------------------
extern "C" void kernel_launch(void* const* d_in, const int* in_sizes, int n_in,
                              void* d_out, int out_size)
{
    (void)in_sizes; (void)n_in; (void)out_size;
    const float* x      = (const float*)d_in[0];
    const float* adj    = (const float*)d_in[1];
    const float* W_mlp2 = (const float*)d_in[2];
    const float* b_mlp2 = (const float*)d_in[3];
    const float* Wr[3]  = {(const float*)d_in[4], (const float*)d_in[7], (const float*)d_in[10]};
    const float* Wo[3]  = {(const float*)d_in[5], (const float*)d_in[8], (const float*)d_in[11]};
    const float* bs[3]  = {(const float*)d_in[6], (const float*)d_in[9], (const float*)d_in[12]};
    const float* W_mlp1 = (const float*)d_in[13];
    const float* b_mlp1 = (const float*)d_in[14];
    float* out = (float*)d_out;

    bf16 *h0h, *h0l, *h1h, *h1l, *aggh, *aggl, *hTh, *hTl;
    bf16 *xh, *xl, *W2h, *W2l, *W1h, *W1l, *Wrh, *Wrl, *Woh, *Wol, *adjh, *adjl;
    float* part;
    cudaGetSymbolAddress((void**)&h0h,  g_h0h); cudaGetSymbolAddress((void**)&h0l, g_h0l);
    cudaGetSymbolAddress((void**)&h1h,  g_h1h); cudaGetSymbolAddress((void**)&h1l, g_h1l);
    cudaGetSymbolAddress((void**)&aggh, g_aggh); cudaGetSymbolAddress((void**)&aggl, g_aggl);
    cudaGetSymbolAddress((void**)&hTh,  g_hTh); cudaGetSymbolAddress((void**)&hTl, g_hTl);
    cudaGetSymbolAddress((void**)&xh,   g_xh);  cudaGetSymbolAddress((void**)&xl,  g_xl);
    cudaGetSymbolAddress((void**)&W2h,  g_W2h); cudaGetSymbolAddress((void**)&W2l, g_W2l);
    cudaGetSymbolAddress((void**)&W1h,  g_W1h); cudaGetSymbolAddress((void**)&W1l, g_W1l);
    cudaGetSymbolAddress((void**)&Wrh,  g_Wrh); cudaGetSymbolAddress((void**)&Wrl, g_Wrl);
    cudaGetSymbolAddress((void**)&Woh,  g_Woh); cudaGetSymbolAddress((void**)&Wol, g_Wol);
    cudaGetSymbolAddress((void**)&adjh, g_adjh); cudaGetSymbolAddress((void**)&adjl, g_adjl);
    cudaGetSymbolAddress((void**)&part, g_part);
    const size_t sPart = (size_t)MT * Dd;
    float *p0 = part, *p1 = part + sPart, *p2 = part + 2 * sPart, *p3 = part + 3 * sPart;

    cudaFuncSetAttribute(gemm_bf<false, false, false, false, false, false, true >,
                         cudaFuncAttributeMaxDynamicSharedMemorySize, GEMM_SMEM);
    cudaFuncSetAttribute(gemm_bf<true,  true,  true,  false, true,  true,  false>,
                         cudaFuncAttributeMaxDynamicSharedMemorySize, GEMM_SMEM);
    cudaFuncSetAttribute(gemm_bf<true,  false, true,  false, true,  false, false>,
                         cudaFuncAttributeMaxDynamicSharedMemorySize, GEMM_SMEM);
    cudaFuncSetAttribute(gemm_bf<false, false, true,  true,  false, false, false>,
                         cudaFuncAttributeMaxDynamicSharedMemorySize, GEMM_SMEM);

    const size_t sHD = (size_t)Nn * Dd;

    // preprocessing
    adj_fused<<<Nn, 256>>>(adj);
    x_split_kernel<<<(MT * LD_ / 2) / 256, 256>>>((const float2*)x);
    wtrans_all<<<480, dim3(32, 8)>>>(W_mlp2, W_mlp1, Wr[0], Wo[0], Wr[1], Wo[1], Wr[2], Wo[2]);

    // mlp2 split-K 2: partials = x @ W_mlp2; grid 256
    gemm_bf<false, false, false, false, false, false, true>
        <<<dim3(Dd / BN, MT / BM, 2), 256, GEMM_SMEM>>>(
        xh, xl, W2h, W2l, nullptr, nullptr, nullptr, nullptr,
        nullptr, part, nullptr, nullptr, nullptr, nullptr,
        Dd, LD_, LD_ / 2, 0, 0, 0, 0, 0, sPart);
    reduce_k<true, true><<<(MT * Dd / 2) / 256, 256>>>(
        (const float2*)p0, (const float2*)p1, b_mlp2, h0h, h0l, hTh, hTl);

    bf16* hinh = h0h; bf16* hinl = h0l;
    bf16* houth = h1h; bf16* houtl = h1l;
    for (int l = 0; l < 3; l++) {
        // agg partials = adjn @ hin (split-K 4 per batch; grid 512)
        gemm_bf<false, false, false, false, false, false, true>
            <<<dim3(Dd / BN, Nn / BM, Bb * 4), 256, GEMM_SMEM>>>(
            adjh, adjl, hTh, hTl, nullptr, nullptr, nullptr, nullptr,
            nullptr, part, nullptr, nullptr, nullptr, nullptr,
            Dd, Nn, Nn / 4, 3, 2, 0, sHD, sHD, sPart);
        reduce_k4<<<(MT * Dd / 2) / 256, 256>>>(
            (const float2*)p0, (const float2*)p1, (const float2*)p2, (const float2*)p3,
            aggh, aggl);
        // h' = act(agg@Wr + hin@Wo + b)   grid 128
        if (l < 2)
            gemm_bf<true, true, true, false, true, true, false>
                <<<dim3(Dd / BN, MT / BM, 1), 256, GEMM_SMEM>>>(
                aggh, aggl, Wrh + l * Dd * Dd, Wrl + l * Dd * Dd,
                hinh, hinl, Woh + l * Dd * Dd, Wol + l * Dd * Dd,
                bs[l], nullptr, houth, houtl, hTh, hTl,
                Dd, Dd, Dd, 0, 0, 0, 0, 0, 0);
        else
            gemm_bf<true, false, true, false, true, false, false>
                <<<dim3(Dd / BN, MT / BM, 1), 256, GEMM_SMEM>>>(
                aggh, aggl, Wrh + l * Dd * Dd, Wrl + l * Dd * Dd,
                hinh, hinl, Woh + l * Dd * Dd, Wol + l * Dd * Dd,
                bs[l], nullptr, houth, houtl, nullptr, nullptr,
                Dd, Dd, Dd, 0, 0, 0, 0, 0, 0);
        { bf16* t = hinh; hinh = houth; houth = t; }
        { bf16* t = hinl; hinl = houtl; houtl = t; }
    }

    // mlp1: out = hin @ W_mlp1 + b   (grid 1536)
    gemm_bf<false, false, true, true, false, false, false>
        <<<dim3(LD_ / BN, MT / BM, 1), 256, GEMM_SMEM>>>(
        hinh, hinl, W1h, W1l, nullptr, nullptr, nullptr, nullptr,
        b_mlp1, out, nullptr, nullptr, nullptr, nullptr,
        LD_, Dd, Dd, 0, 0, 0, 0, 0, 0);
}

// round 11
// speedup vs baseline: 1.0020x; 1.0020x over previous
#include <cuda_runtime.h>
#include <cuda_bf16.h>
#include <cstdint>

#define Bb   4
#define Nn   2048
#define Ll   12
#define Dd   128
#define LD_  (Ll*Dd)      // 1536
#define MT   (Bb*Nn)      // 8192

typedef __nv_bfloat16 bf16;

// ---------------- scratch (device globals; no allocation) -------------------
__device__ bf16  g_h0h[MT * Dd];  __device__ bf16 g_h0l[MT * Dd];
__device__ bf16  g_h1h[MT * Dd];  __device__ bf16 g_h1l[MT * Dd];
__device__ bf16  g_aggh[MT * Dd]; __device__ bf16 g_aggl[MT * Dd];
__device__ bf16  g_hTh[Bb * Dd * Nn]; __device__ bf16 g_hTl[Bb * Dd * Nn];
__device__ bf16  g_adjh[Nn * Nn]; __device__ bf16 g_adjl[Nn * Nn];
__device__ bf16  g_xh [MT * LD_]; __device__ bf16 g_xl [MT * LD_];
__device__ bf16  g_W2h[Dd * LD_]; __device__ bf16 g_W2l[Dd * LD_];
__device__ bf16  g_W1h[LD_ * Dd]; __device__ bf16 g_W1l[LD_ * Dd];
__device__ bf16  g_Wrh[3][Dd * Dd]; __device__ bf16 g_Wrl[3][Dd * Dd];
__device__ bf16  g_Woh[3][Dd * Dd]; __device__ bf16 g_Wol[3][Dd * Dd];
__device__ float g_part[4][MT * Dd];   // split-K partials (16 MB)

// ---------------- helpers ----------------------------------------------------
__device__ __forceinline__ uint32_t smem_u32(const void* p) {
    uint32_t a;
    asm("{ .reg .u64 t; cvta.to.shared.u64 t, %1; cvt.u32.u64 %0, t; }"
        : "=r"(a) : "l"(p));
    return a;
}
__device__ __forceinline__ void cp_async16(uint32_t dst, const void* src) {
    asm volatile("cp.async.cg.shared.global [%0], [%1], 16;"
                 :: "r"(dst), "l"(src) : "memory");
}
__device__ __forceinline__ void cp_commit() {
    asm volatile("cp.async.commit_group;" ::: "memory");
}
template<int N_>
__device__ __forceinline__ void cp_wait() {
    asm volatile("cp.async.wait_group %0;" :: "n"(N_) : "memory");
}
__device__ __forceinline__ void ldmx4(uint32_t* r, uint32_t addr) {
    asm volatile("ldmatrix.sync.aligned.m8n8.x4.shared.b16 {%0,%1,%2,%3}, [%4];"
                 : "=r"(r[0]), "=r"(r[1]), "=r"(r[2]), "=r"(r[3]) : "r"(addr));
}
__device__ __forceinline__ void mma_bf16(float* c, const uint32_t* a, const uint32_t* b) {
    asm volatile(
        "mma.sync.aligned.m16n8k16.row.col.f32.bf16.bf16.f32 "
        "{%0,%1,%2,%3}, {%4,%5,%6,%7}, {%8,%9}, {%0,%1,%2,%3};"
        : "+f"(c[0]), "+f"(c[1]), "+f"(c[2]), "+f"(c[3])
        : "r"(a[0]), "r"(a[1]), "r"(a[2]), "r"(a[3]), "r"(b[0]), "r"(b[1]));
}
__device__ __forceinline__ void split2(float v, bf16& h, bf16& l) {
    h = __float2bfloat16(v);
    l = __float2bfloat16(v - __bfloat162float(h));
}

// ---------------- fused preprocessing ------------------------------------------
__global__ void adj_fused(const float* __restrict__ adj) {
    const int row = blockIdx.x;
    const int tid = threadIdx.x;
    const float* r = adj + (size_t)row * Nn;
    float v[8]; float s = 0.f;
    #pragma unroll
    for (int i = 0; i < 8; i++) { v[i] = r[tid + i * 256]; s += v[i]; }
    __shared__ float sm[8];
    #pragma unroll
    for (int o = 16; o > 0; o >>= 1) s += __shfl_down_sync(0xffffffffu, s, o);
    if ((tid & 31) == 0) sm[tid >> 5] = s;
    __syncthreads();
    __shared__ float rdeg;
    if (tid == 0) {
        float t = 0.f;
        #pragma unroll
        for (int i = 0; i < 8; i++) t += sm[i];
        rdeg = 1.0f / fmaxf(t, 1.0f);
    }
    __syncthreads();
    const float rd = rdeg;
    #pragma unroll
    for (int i = 0; i < 8; i++) {
        bf16 h, l;
        split2(v[i] * rd, h, l);
        size_t o = (size_t)row * Nn + tid + i * 256;
        g_adjh[o] = h; g_adjl[o] = l;
    }
}

__global__ void x_split_kernel(const float2* __restrict__ in) {
    int idx = blockIdx.x * blockDim.x + threadIdx.x;
    float2 v = in[idx];
    bf16 h0, l0, h1, l1;
    split2(v.x, h0, l0); split2(v.y, h1, l1);
    *reinterpret_cast<__nv_bfloat162*>(&g_xh[2 * idx]) = __nv_bfloat162(h0, h1);
    *reinterpret_cast<__nv_bfloat162*>(&g_xl[2 * idx]) = __nv_bfloat162(l0, l1);
}

__global__ void wtrans_all(const float* __restrict__ W2, const float* __restrict__ W1,
                           const float* __restrict__ Wr0, const float* __restrict__ Wo0,
                           const float* __restrict__ Wr1, const float* __restrict__ Wo1,
                           const float* __restrict__ Wr2, const float* __restrict__ Wo2)
{
    __shared__ float t[32][33];
    const int tb = blockIdx.x;
    const float* src; bf16* dh; bf16* dl; int R, C, tx, ty;
    if (tb < 192) {
        src = W2; dh = g_W2h; dl = g_W2l; R = LD_; C = Dd;
        ty = tb / 4; tx = tb % 4;
    } else if (tb < 384) {
        src = W1; dh = g_W1h; dl = g_W1l; R = Dd; C = LD_;
        int u = tb - 192; ty = u / 48; tx = u % 48;
    } else {
        int u = tb - 384; int l = u / 32; int v = u % 32;
        const float* wsrc[6] = {Wr0, Wo0, Wr1, Wo1, Wr2, Wo2};
        src = wsrc[l * 2 + (v < 16 ? 0 : 1)];
        if (v < 16) { dh = g_Wrh[l]; dl = g_Wrl[l]; }
        else        { dh = g_Woh[l]; dl = g_Wol[l]; }
        int w = v & 15; tx = w % 4; ty = w / 4; R = Dd; C = Dd;
    }
    const int c0 = tx * 32, r0 = ty * 32;
    const int x = threadIdx.x, y = threadIdx.y;
    #pragma unroll
    for (int i = 0; i < 32; i += 8)
        t[y + i][x] = src[(size_t)(r0 + y + i) * C + c0 + x];
    __syncthreads();
    #pragma unroll
    for (int i = 0; i < 32; i += 8) {
        bf16 h, l;
        split2(t[x][y + i], h, l);
        size_t o = (size_t)(c0 + y + i) * R + r0 + x;
        dh[o] = h; dl[o] = l;
    }
}

// ---------------- split-K reductions --------------------------------------------
template<bool BIAS, bool WT>
__global__ void reduce_k(const float2* __restrict__ p0, const float2* __restrict__ p1,
                         const float* __restrict__ bias,
                         bf16* __restrict__ Ch, bf16* __restrict__ Cl,
                         bf16* __restrict__ Th, bf16* __restrict__ Tl)
{
    const int idx = blockIdx.x * blockDim.x + threadIdx.x;   // over MT*Dd/2
    float2 a = p0[idx], b = p1[idx];
    float v0 = a.x + b.x, v1 = a.y + b.y;
    const int col = (2 * idx) & 127;
    if (BIAS) { v0 += bias[col]; v1 += bias[col + 1]; }
    bf16 h0, l0, h1, l1;
    split2(v0, h0, l0); split2(v1, h1, l1);
    *reinterpret_cast<__nv_bfloat162*>(Ch + 2 * idx) = __nv_bfloat162(h0, h1);
    *reinterpret_cast<__nv_bfloat162*>(Cl + 2 * idx) = __nv_bfloat162(l0, l1);
    if (WT) {
        const int row = (2 * idx) >> 7;
        const int bb_ = row >> 11, nn_ = row & 2047;
        const size_t ot = (size_t)bb_ * (Dd * (size_t)Nn) + (size_t)col * Nn + nn_;
        Th[ot] = h0;      Tl[ot] = l0;
        Th[ot + Nn] = h1; Tl[ot + Nn] = l1;
    }
}

__global__ void reduce_k4(const float2* __restrict__ p0, const float2* __restrict__ p1,
                          const float2* __restrict__ p2, const float2* __restrict__ p3,
                          bf16* __restrict__ Ch, bf16* __restrict__ Cl)
{
    const int idx = blockIdx.x * blockDim.x + threadIdx.x;   // over MT*Dd/2
    float2 a = p0[idx], b = p1[idx], c = p2[idx], d = p3[idx];
    float v0 = (a.x + b.x) + (c.x + d.x);
    float v1 = (a.y + b.y) + (c.y + d.y);
    bf16 h0, l0, h1, l1;
    split2(v0, h0, l0); split2(v1, h1, l1);
    *reinterpret_cast<__nv_bfloat162*>(Ch + 2 * idx) = __nv_bfloat162(h0, h1);
    *reinterpret_cast<__nv_bfloat162*>(Cl + 2 * idx) = __nv_bfloat162(l0, l1);
}

// ---------------- bf16x2 tensor-core GEMM -------------------------------------
// R9 body; STAGES 3->2 and launch_bounds occupancy 2->3 to fit 3 CTAs/SM
// (smem 2*30720*2 = 61440B/CTA -> 3 fit in 228KB; regs forced <=85).
#define STAGES 2
#define BM 64
#define BN 128
#define BK 32
#define KS2 40
#define OFF_AL (64 * KS2)
#define OFF_BH (2 * 64 * KS2)
#define OFF_BL (OFF_BH + 128 * KS2)
#define STAGE_H (OFF_BL + 128 * KS2)
#define GEMM_SMEM (STAGES * STAGE_H * 2)    // 61440 B

template<bool DUAL, bool RELU, bool BIAS, bool WF32, bool WSPL, bool WT, bool SPLITK>
__global__ void __launch_bounds__(256, 3)
gemm_bf(const bf16* __restrict__ Ah, const bf16* __restrict__ Al,
        const bf16* __restrict__ Bh, const bf16* __restrict__ Bl,
        const bf16* __restrict__ A2h, const bf16* __restrict__ A2l,
        const bf16* __restrict__ B2h, const bf16* __restrict__ B2l,
        const float* __restrict__ bias,
        float* __restrict__ Cf, bf16* __restrict__ Ch, bf16* __restrict__ Cl,
        bf16* __restrict__ Th, bf16* __restrict__ Tl,
        int N, int ldK, int kLen, int zmask, int zshift,
        size_t sA, size_t sB, size_t sC, size_t sPart)
{
    extern __shared__ bf16 smem[];
    const uint32_t sbase = smem_u32(smem);
    const int tid = threadIdx.x;
    const int lane = tid & 31, wid = tid >> 5;
    const int warpM = wid & 1, warpN = wid >> 1;
    const int gid = lane >> 2, tg = lane & 3;

    const int m0 = blockIdx.y * BM, n0 = blockIdx.x * BN;
    int batch, split, kOff;
    if (SPLITK) { batch = blockIdx.z & zmask; split = blockIdx.z >> zshift;
                  kOff = split * kLen; }
    else        { batch = blockIdx.z; split = 0; kOff = 0; }

    const bf16* pAh = Ah + (size_t)batch * sA;
    const bf16* pAl = Al + (size_t)batch * sA;
    const bf16* pBh = Bh + (size_t)batch * sB;
    const bf16* pBl = Bl + (size_t)batch * sB;

    const int nk1 = kLen / BK;
    const int nk  = DUAL ? 2 * nk1 : nk1;

    auto issue = [&](int tile, int s) {
        const bf16 *ah, *al, *bh, *bl; int k0;
        if (DUAL && tile >= nk1) { ah = A2h; al = A2l; bh = B2h; bl = B2l;
                                   k0 = (tile - nk1) * BK; }
        else { ah = pAh; al = pAl; bh = pBh; bl = pBl; k0 = kOff + tile * BK; }
        const uint32_t st = sbase + s * (STAGE_H * 2);
        {
            int row = tid >> 2, c = tid & 3;
            uint32_t dof = (uint32_t)(row * KS2 + c * 8) * 2;
            size_t gof = (size_t)(m0 + row) * ldK + k0 + c * 8;
            cp_async16(st + dof,              ah + gof);
            cp_async16(st + OFF_AL * 2 + dof, al + gof);
        }
        #pragma unroll
        for (int i = 0; i < 2; i++) {
            int idx = tid + i * 256;
            int row = idx >> 2, c = idx & 3;
            uint32_t dof = (uint32_t)(row * KS2 + c * 8) * 2;
            size_t gof = (size_t)(n0 + row) * ldK + k0 + c * 8;
            cp_async16(st + OFF_BH * 2 + dof, bh + gof);
            cp_async16(st + OFF_BL * 2 + dof, bl + gof);
        }
        cp_commit();
    };

    float acc[2][4][4];
    #pragma unroll
    for (int mi = 0; mi < 2; mi++)
        #pragma unroll
        for (int ni = 0; ni < 4; ni++)
            #pragma unroll
            for (int j = 0; j < 4; j++) acc[mi][ni][j] = 0.f;

    const int ar = lane & 15, ak = (lane >> 4) * 8;
    const uint32_t a_off = (uint32_t)((warpM * 32 + ar) * KS2 + ak) * 2;
    const int nr = (lane & 7) + ((lane >> 4) * 8);
    const int bk = ((lane >> 3) & 1) * 8;
    const uint32_t b_off = (uint32_t)((warpN * 32 + nr) * KS2 + bk) * 2;

    #pragma unroll
    for (int s = 0; s < STAGES - 1; s++) issue(s, s);

    for (int kt = 0; kt < nk; ++kt) {
        cp_wait<STAGES - 2>();
        __syncthreads();
        if (kt + STAGES - 1 < nk) issue(kt + STAGES - 1, (kt + STAGES - 1) % STAGES);

        const uint32_t st = sbase + (kt % STAGES) * (STAGE_H * 2);
        const uint32_t aA = st + a_off;
        const uint32_t aB = st + OFF_BH * 2 + b_off;

        #pragma unroll
        for (int ks = 0; ks < 2; ks++) {
            const uint32_t ko = ks * 32;
            uint32_t ah_[2][4], al_[2][4], bh_[2][4], bl_[2][4];
            #pragma unroll
            for (int mi = 0; mi < 2; mi++) {
                ldmx4(ah_[mi], aA + mi * (16 * KS2 * 2) + ko);
                ldmx4(al_[mi], aA + OFF_AL * 2 + mi * (16 * KS2 * 2) + ko);
            }
            #pragma unroll
            for (int np = 0; np < 2; np++) {
                ldmx4(bh_[np], aB + np * (16 * KS2 * 2) + ko);
                ldmx4(bl_[np], aB + (OFF_BL - OFF_BH) * 2 + np * (16 * KS2 * 2) + ko);
            }
            #pragma unroll
            for (int mi = 0; mi < 2; mi++)
                #pragma unroll
                for (int ni = 0; ni < 4; ni++) {
                    const int np = ni >> 1, jo = (ni & 1) * 2;
                    mma_bf16(acc[mi][ni], ah_[mi], &bh_[np][jo]);
                    mma_bf16(acc[mi][ni], ah_[mi], &bl_[np][jo]);
                    mma_bf16(acc[mi][ni], al_[mi], &bh_[np][jo]);
                }
        }
    }
    cp_wait<0>();

    // epilogue
    const size_t obase = (SPLITK ? (size_t)split * sPart : 0) + (size_t)batch * sC;
    #pragma unroll
    for (int mi = 0; mi < 2; mi++) {
        const int rbase = m0 + warpM * 32 + mi * 16 + gid;
        #pragma unroll
        for (int ni = 0; ni < 4; ni++) {
            const int col = n0 + warpN * 32 + ni * 8 + 2 * tg;
            float* c = acc[mi][ni];
            float b0 = 0.f, b1 = 0.f;
            if (BIAS) { b0 = bias[col]; b1 = bias[col + 1]; }
            #pragma unroll
            for (int h2 = 0; h2 < 2; h2++) {
                const int row = rbase + 8 * h2;
                float v0 = c[2 * h2 + 0] + b0;
                float v1 = c[2 * h2 + 1] + b1;
                if (RELU) { v0 = fmaxf(v0, 0.f); v1 = fmaxf(v1, 0.f); }
                const size_t o = obase + (size_t)row * N + col;
                if (SPLITK || WF32)
                    *reinterpret_cast<float2*>(Cf + o) = make_float2(v0, v1);
                if (WSPL || WT) {
                    bf16 h0_, l0_, h1_, l1_;
                    split2(v0, h0_, l0_); split2(v1, h1_, l1_);
                    if (WSPL) {
                        *reinterpret_cast<__nv_bfloat162*>(Ch + o) = __nv_bfloat162(h0_, h1_);
                        *reinterpret_cast<__nv_bfloat162*>(Cl + o) = __nv_bfloat162(l0_, l1_);
                    }
                    if (WT) {
                        const int bb_ = row >> 11, nn_ = row & 2047;
                        const size_t ot = (size_t)bb_ * (Dd * (size_t)Nn)
                                        + (size_t)col * Nn + nn_;
                        Th[ot] = h0_;      Tl[ot] = l0_;
                        Th[ot + Nn] = h1_; Tl[ot + Nn] = l1_;
                    }
                }
            }
        }
    }
}

// ---------------- launch --------------------------------------------------------
extern "C" void kernel_launch(void* const* d_in, const int* in_sizes, int n_in,
                              void* d_out, int out_size)
{
    (void)in_sizes; (void)n_in; (void)out_size;
    const float* x      = (const float*)d_in[0];
    const float* adj    = (const float*)d_in[1];
    const float* W_mlp2 = (const float*)d_in[2];
    const float* b_mlp2 = (const float*)d_in[3];
    const float* Wr[3]  = {(const float*)d_in[4], (const float*)d_in[7], (const float*)d_in[10]};
    const float* Wo[3]  = {(const float*)d_in[5], (const float*)d_in[8], (const float*)d_in[11]};
    const float* bs[3]  = {(const float*)d_in[6], (const float*)d_in[9], (const float*)d_in[12]};
    const float* W_mlp1 = (const float*)d_in[13];
    const float* b_mlp1 = (const float*)d_in[14];
    float* out = (float*)d_out;

    bf16 *h0h, *h0l, *h1h, *h1l, *aggh, *aggl, *hTh, *hTl;
    bf16 *xh, *xl, *W2h, *W2l, *W1h, *W1l, *Wrh, *Wrl, *Woh, *Wol, *adjh, *adjl;
    float* part;
    cudaGetSymbolAddress((void**)&h0h,  g_h0h); cudaGetSymbolAddress((void**)&h0l, g_h0l);
    cudaGetSymbolAddress((void**)&h1h,  g_h1h); cudaGetSymbolAddress((void**)&h1l, g_h1l);
    cudaGetSymbolAddress((void**)&aggh, g_aggh); cudaGetSymbolAddress((void**)&aggl, g_aggl);
    cudaGetSymbolAddress((void**)&hTh,  g_hTh); cudaGetSymbolAddress((void**)&hTl, g_hTl);
    cudaGetSymbolAddress((void**)&xh,   g_xh);  cudaGetSymbolAddress((void**)&xl,  g_xl);
    cudaGetSymbolAddress((void**)&W2h,  g_W2h); cudaGetSymbolAddress((void**)&W2l, g_W2l);
    cudaGetSymbolAddress((void**)&W1h,  g_W1h); cudaGetSymbolAddress((void**)&W1l, g_W1l);
    cudaGetSymbolAddress((void**)&Wrh,  g_Wrh); cudaGetSymbolAddress((void**)&Wrl, g_Wrl);
    cudaGetSymbolAddress((void**)&Woh,  g_Woh); cudaGetSymbolAddress((void**)&Wol, g_Wol);
    cudaGetSymbolAddress((void**)&adjh, g_adjh); cudaGetSymbolAddress((void**)&adjl, g_adjl);
    cudaGetSymbolAddress((void**)&part, g_part);
    const size_t sPart = (size_t)MT * Dd;
    float *p0 = part, *p1 = part + sPart, *p2 = part + 2 * sPart, *p3 = part + 3 * sPart;

    cudaFuncSetAttribute(gemm_bf<false, false, false, false, false, false, true >,
                         cudaFuncAttributeMaxDynamicSharedMemorySize, GEMM_SMEM);
    cudaFuncSetAttribute(gemm_bf<true,  true,  true,  false, true,  true,  false>,
                         cudaFuncAttributeMaxDynamicSharedMemorySize, GEMM_SMEM);
    cudaFuncSetAttribute(gemm_bf<true,  false, true,  false, true,  false, false>,
                         cudaFuncAttributeMaxDynamicSharedMemorySize, GEMM_SMEM);
    cudaFuncSetAttribute(gemm_bf<false, false, true,  true,  false, false, false>,
                         cudaFuncAttributeMaxDynamicSharedMemorySize, GEMM_SMEM);

    const size_t sHD = (size_t)Nn * Dd;

    // preprocessing
    adj_fused<<<Nn, 256>>>(adj);
    x_split_kernel<<<(MT * LD_ / 2) / 256, 256>>>((const float2*)x);
    wtrans_all<<<480, dim3(32, 8)>>>(W_mlp2, W_mlp1, Wr[0], Wo[0], Wr[1], Wo[1], Wr[2], Wo[2]);

    // mlp2 split-K 2: partials = x @ W_mlp2; grid 256
    gemm_bf<false, false, false, false, false, false, true>
        <<<dim3(Dd / BN, MT / BM, 2), 256, GEMM_SMEM>>>(
        xh, xl, W2h, W2l, nullptr, nullptr, nullptr, nullptr,
        nullptr, part, nullptr, nullptr, nullptr, nullptr,
        Dd, LD_, LD_ / 2, 0, 0, 0, 0, 0, sPart);
    reduce_k<true, true><<<(MT * Dd / 2) / 256, 256>>>(
        (const float2*)p0, (const float2*)p1, b_mlp2, h0h, h0l, hTh, hTl);

    bf16* hinh = h0h; bf16* hinl = h0l;
    bf16* houth = h1h; bf16* houtl = h1l;
    for (int l = 0; l < 3; l++) {
        // agg partials = adjn @ hin (split-K 4 per batch; grid 512)
        gemm_bf<false, false, false, false, false, false, true>
            <<<dim3(Dd / BN, Nn / BM, Bb * 4), 256, GEMM_SMEM>>>(
            adjh, adjl, hTh, hTl, nullptr, nullptr, nullptr, nullptr,
            nullptr, part, nullptr, nullptr, nullptr, nullptr,
            Dd, Nn, Nn / 4, 3, 2, 0, sHD, sHD, sPart);
        reduce_k4<<<(MT * Dd / 2) / 256, 256>>>(
            (const float2*)p0, (const float2*)p1, (const float2*)p2, (const float2*)p3,
            aggh, aggl);
        // h' = act(agg@Wr + hin@Wo + b)   grid 128
        if (l < 2)
            gemm_bf<true, true, true, false, true, true, false>
                <<<dim3(Dd / BN, MT / BM, 1), 256, GEMM_SMEM>>>(
                aggh, aggl, Wrh + l * Dd * Dd, Wrl + l * Dd * Dd,
                hinh, hinl, Woh + l * Dd * Dd, Wol + l * Dd * Dd,
                bs[l], nullptr, houth, houtl, hTh, hTl,
                Dd, Dd, Dd, 0, 0, 0, 0, 0, 0);
        else
            gemm_bf<true, false, true, false, true, false, false>
                <<<dim3(Dd / BN, MT / BM, 1), 256, GEMM_SMEM>>>(
                aggh, aggl, Wrh + l * Dd * Dd, Wrl + l * Dd * Dd,
                hinh, hinl, Woh + l * Dd * Dd, Wol + l * Dd * Dd,
                bs[l], nullptr, houth, houtl, nullptr, nullptr,
                Dd, Dd, Dd, 0, 0, 0, 0, 0, 0);
        { bf16* t = hinh; hinh = houth; houth = t; }
        { bf16* t = hinl; hinl = houtl; houtl = t; }
    }

    // mlp1: out = hin @ W_mlp1 + b   (grid 1536)
    gemm_bf<false, false, true, true, false, false, false>
        <<<dim3(LD_ / BN, MT / BM, 1), 256, GEMM_SMEM>>>(
        hinh, hinl, W1h, W1l, nullptr, nullptr, nullptr, nullptr,
        b_mlp1, out, nullptr, nullptr, nullptr, nullptr,
        LD_, Dd, Dd, 0, 0, 0, 0, 0, 0);
}

// round 12
// speedup vs baseline: 1.0697x; 1.0676x over previous
#include <cuda_runtime.h>
#include <cuda_bf16.h>
#include <cstdint>

#define Bb   4
#define Nn   2048
#define Ll   12
#define Dd   128
#define LD_  (Ll*Dd)      // 1536
#define MT   (Bb*Nn)      // 8192

typedef __nv_bfloat16 bf16;

// ---------------- scratch (device globals; no allocation) -------------------
__device__ bf16  g_h0h[MT * Dd];  __device__ bf16 g_h0l[MT * Dd];
__device__ bf16  g_h1h[MT * Dd];  __device__ bf16 g_h1l[MT * Dd];
__device__ bf16  g_aggh[MT * Dd]; __device__ bf16 g_aggl[MT * Dd];
__device__ bf16  g_hTh[Bb * Dd * Nn]; __device__ bf16 g_hTl[Bb * Dd * Nn];
__device__ bf16  g_adjh[Nn * Nn]; __device__ bf16 g_adjl[Nn * Nn];
__device__ bf16  g_xh [MT * LD_]; __device__ bf16 g_xl [MT * LD_];
__device__ bf16  g_W2h[Dd * LD_]; __device__ bf16 g_W2l[Dd * LD_];
__device__ bf16  g_W1h[LD_ * Dd]; __device__ bf16 g_W1l[LD_ * Dd];
__device__ bf16  g_Wrh[3][Dd * Dd]; __device__ bf16 g_Wrl[3][Dd * Dd];
__device__ bf16  g_Woh[3][Dd * Dd]; __device__ bf16 g_Wol[3][Dd * Dd];
__device__ float g_part[4][MT * Dd];   // split-K partials (16 MB)

// ---------------- helpers ----------------------------------------------------
__device__ __forceinline__ uint32_t smem_u32(const void* p) {
    uint32_t a;
    asm("{ .reg .u64 t; cvta.to.shared.u64 t, %1; cvt.u32.u64 %0, t; }"
        : "=r"(a) : "l"(p));
    return a;
}
__device__ __forceinline__ void cp_async16(uint32_t dst, const void* src) {
    asm volatile("cp.async.cg.shared.global [%0], [%1], 16;"
                 :: "r"(dst), "l"(src) : "memory");
}
__device__ __forceinline__ void cp_commit() {
    asm volatile("cp.async.commit_group;" ::: "memory");
}
template<int N_>
__device__ __forceinline__ void cp_wait() {
    asm volatile("cp.async.wait_group %0;" :: "n"(N_) : "memory");
}
__device__ __forceinline__ void ldmx4(uint32_t* r, uint32_t addr) {
    asm volatile("ldmatrix.sync.aligned.m8n8.x4.shared.b16 {%0,%1,%2,%3}, [%4];"
                 : "=r"(r[0]), "=r"(r[1]), "=r"(r[2]), "=r"(r[3]) : "r"(addr));
}
__device__ __forceinline__ void mma_bf16(float* c, const uint32_t* a, const uint32_t* b) {
    asm volatile(
        "mma.sync.aligned.m16n8k16.row.col.f32.bf16.bf16.f32 "
        "{%0,%1,%2,%3}, {%4,%5,%6,%7}, {%8,%9}, {%0,%1,%2,%3};"
        : "+f"(c[0]), "+f"(c[1]), "+f"(c[2]), "+f"(c[3])
        : "r"(a[0]), "r"(a[1]), "r"(a[2]), "r"(a[3]), "r"(b[0]), "r"(b[1]));
}
__device__ __forceinline__ void split2(float v, bf16& h, bf16& l) {
    h = __float2bfloat16(v);
    l = __float2bfloat16(v - __bfloat162float(h));
}

// ---------------- fused preprocessing ------------------------------------------
__global__ void adj_fused(const float* __restrict__ adj) {
    const int row = blockIdx.x;
    const int tid = threadIdx.x;
    const float* r = adj + (size_t)row * Nn;
    float v[8]; float s = 0.f;
    #pragma unroll
    for (int i = 0; i < 8; i++) { v[i] = r[tid + i * 256]; s += v[i]; }
    __shared__ float sm[8];
    #pragma unroll
    for (int o = 16; o > 0; o >>= 1) s += __shfl_down_sync(0xffffffffu, s, o);
    if ((tid & 31) == 0) sm[tid >> 5] = s;
    __syncthreads();
    __shared__ float rdeg;
    if (tid == 0) {
        float t = 0.f;
        #pragma unroll
        for (int i = 0; i < 8; i++) t += sm[i];
        rdeg = 1.0f / fmaxf(t, 1.0f);
    }
    __syncthreads();
    const float rd = rdeg;
    #pragma unroll
    for (int i = 0; i < 8; i++) {
        bf16 h, l;
        split2(v[i] * rd, h, l);
        size_t o = (size_t)row * Nn + tid + i * 256;
        g_adjh[o] = h; g_adjl[o] = l;
    }
}

__global__ void x_split_kernel(const float2* __restrict__ in) {
    int idx = blockIdx.x * blockDim.x + threadIdx.x;
    float2 v = in[idx];
    bf16 h0, l0, h1, l1;
    split2(v.x, h0, l0); split2(v.y, h1, l1);
    *reinterpret_cast<__nv_bfloat162*>(&g_xh[2 * idx]) = __nv_bfloat162(h0, h1);
    *reinterpret_cast<__nv_bfloat162*>(&g_xl[2 * idx]) = __nv_bfloat162(l0, l1);
}

__global__ void wtrans_all(const float* __restrict__ W2, const float* __restrict__ W1,
                           const float* __restrict__ Wr0, const float* __restrict__ Wo0,
                           const float* __restrict__ Wr1, const float* __restrict__ Wo1,
                           const float* __restrict__ Wr2, const float* __restrict__ Wo2)
{
    __shared__ float t[32][33];
    const int tb = blockIdx.x;
    const float* src; bf16* dh; bf16* dl; int R, C, tx, ty;
    if (tb < 192) {
        src = W2; dh = g_W2h; dl = g_W2l; R = LD_; C = Dd;
        ty = tb / 4; tx = tb % 4;
    } else if (tb < 384) {
        src = W1; dh = g_W1h; dl = g_W1l; R = Dd; C = LD_;
        int u = tb - 192; ty = u / 48; tx = u % 48;
    } else {
        int u = tb - 384; int l = u / 32; int v = u % 32;
        const float* wsrc[6] = {Wr0, Wo0, Wr1, Wo1, Wr2, Wo2};
        src = wsrc[l * 2 + (v < 16 ? 0 : 1)];
        if (v < 16) { dh = g_Wrh[l]; dl = g_Wrl[l]; }
        else        { dh = g_Woh[l]; dl = g_Wol[l]; }
        int w = v & 15; tx = w % 4; ty = w / 4; R = Dd; C = Dd;
    }
    const int c0 = tx * 32, r0 = ty * 32;
    const int x = threadIdx.x, y = threadIdx.y;
    #pragma unroll
    for (int i = 0; i < 32; i += 8)
        t[y + i][x] = src[(size_t)(r0 + y + i) * C + c0 + x];
    __syncthreads();
    #pragma unroll
    for (int i = 0; i < 32; i += 8) {
        bf16 h, l;
        split2(t[x][y + i], h, l);
        size_t o = (size_t)(c0 + y + i) * R + r0 + x;
        dh[o] = h; dl[o] = l;
    }
}

// ---------------- split-K reductions --------------------------------------------
template<bool BIAS, bool WT>
__global__ void reduce_k(const float2* __restrict__ p0, const float2* __restrict__ p1,
                         const float* __restrict__ bias,
                         bf16* __restrict__ Ch, bf16* __restrict__ Cl,
                         bf16* __restrict__ Th, bf16* __restrict__ Tl)
{
    const int idx = blockIdx.x * blockDim.x + threadIdx.x;   // over MT*Dd/2
    float2 a = p0[idx], b = p1[idx];
    float v0 = a.x + b.x, v1 = a.y + b.y;
    const int col = (2 * idx) & 127;
    if (BIAS) { v0 += bias[col]; v1 += bias[col + 1]; }
    bf16 h0, l0, h1, l1;
    split2(v0, h0, l0); split2(v1, h1, l1);
    *reinterpret_cast<__nv_bfloat162*>(Ch + 2 * idx) = __nv_bfloat162(h0, h1);
    *reinterpret_cast<__nv_bfloat162*>(Cl + 2 * idx) = __nv_bfloat162(l0, l1);
    if (WT) {
        const int row = (2 * idx) >> 7;
        const int bb_ = row >> 11, nn_ = row & 2047;
        const size_t ot = (size_t)bb_ * (Dd * (size_t)Nn) + (size_t)col * Nn + nn_;
        Th[ot] = h0;      Tl[ot] = l0;
        Th[ot + Nn] = h1; Tl[ot + Nn] = l1;
    }
}

__global__ void reduce_k4(const float2* __restrict__ p0, const float2* __restrict__ p1,
                          const float2* __restrict__ p2, const float2* __restrict__ p3,
                          bf16* __restrict__ Ch, bf16* __restrict__ Cl)
{
    const int idx = blockIdx.x * blockDim.x + threadIdx.x;   // over MT*Dd/2
    float2 a = p0[idx], b = p1[idx], c = p2[idx], d = p3[idx];
    float v0 = (a.x + b.x) + (c.x + d.x);
    float v1 = (a.y + b.y) + (c.y + d.y);
    bf16 h0, l0, h1, l1;
    split2(v0, h0, l0); split2(v1, h1, l1);
    *reinterpret_cast<__nv_bfloat162*>(Ch + 2 * idx) = __nv_bfloat162(h0, h1);
    *reinterpret_cast<__nv_bfloat162*>(Cl + 2 * idx) = __nv_bfloat162(l0, l1);
}

// ---------------- bf16x2 tensor-core GEMM -------------------------------------
// R9 body with BK 32->64: half the barriers, 2 stages (55.3KB each, 2 CTAs/SM).
#define STAGES 2
#define BM 64
#define BN 128
#define BK 64
#define KS2 72                              // 64 + 8 pad (halves); banks verified
#define OFF_AL (64 * KS2)                   // 4608 halves
#define OFF_BH (2 * 64 * KS2)               // 9216
#define OFF_BL (OFF_BH + 128 * KS2)         // 18432
#define STAGE_H (OFF_BL + 128 * KS2)        // 27648 halves = 55296 B
#define GEMM_SMEM (STAGES * STAGE_H * 2)    // 110592 B

template<bool DUAL, bool RELU, bool BIAS, bool WF32, bool WSPL, bool WT, bool SPLITK>
__global__ void __launch_bounds__(256, 2)
gemm_bf(const bf16* __restrict__ Ah, const bf16* __restrict__ Al,
        const bf16* __restrict__ Bh, const bf16* __restrict__ Bl,
        const bf16* __restrict__ A2h, const bf16* __restrict__ A2l,
        const bf16* __restrict__ B2h, const bf16* __restrict__ B2l,
        const float* __restrict__ bias,
        float* __restrict__ Cf, bf16* __restrict__ Ch, bf16* __restrict__ Cl,
        bf16* __restrict__ Th, bf16* __restrict__ Tl,
        int N, int ldK, int kLen, int zmask, int zshift,
        size_t sA, size_t sB, size_t sC, size_t sPart)
{
    extern __shared__ bf16 smem[];
    const uint32_t sbase = smem_u32(smem);
    const int tid = threadIdx.x;
    const int lane = tid & 31, wid = tid >> 5;
    const int warpM = wid & 1, warpN = wid >> 1;
    const int gid = lane >> 2, tg = lane & 3;

    const int m0 = blockIdx.y * BM, n0 = blockIdx.x * BN;
    int batch, split, kOff;
    if (SPLITK) { batch = blockIdx.z & zmask; split = blockIdx.z >> zshift;
                  kOff = split * kLen; }
    else        { batch = blockIdx.z; split = 0; kOff = 0; }

    const bf16* pAh = Ah + (size_t)batch * sA;
    const bf16* pAl = Al + (size_t)batch * sA;
    const bf16* pBh = Bh + (size_t)batch * sB;
    const bf16* pBl = Bl + (size_t)batch * sB;

    const int nk1 = kLen / BK;
    const int nk  = DUAL ? 2 * nk1 : nk1;

    auto issue = [&](int tile, int s) {
        const bf16 *ah, *al, *bh, *bl; int k0;
        if (DUAL && tile >= nk1) { ah = A2h; al = A2l; bh = B2h; bl = B2l;
                                   k0 = (tile - nk1) * BK; }
        else { ah = pAh; al = pAl; bh = pBh; bl = pBl; k0 = kOff + tile * BK; }
        const uint32_t st = sbase + s * (STAGE_H * 2);
        #pragma unroll
        for (int i = 0; i < 2; i++) {   // A: 64 rows x 8 chunks (hi + lo)
            int idx = tid + i * 256;
            int row = idx >> 3, c = idx & 7;
            uint32_t dof = (uint32_t)(row * KS2 + c * 8) * 2;
            size_t gof = (size_t)(m0 + row) * ldK + k0 + c * 8;
            cp_async16(st + dof,              ah + gof);
            cp_async16(st + OFF_AL * 2 + dof, al + gof);
        }
        #pragma unroll
        for (int i = 0; i < 4; i++) {   // B: 128 rows x 8 chunks (hi + lo)
            int idx = tid + i * 256;
            int row = idx >> 3, c = idx & 7;
            uint32_t dof = (uint32_t)(row * KS2 + c * 8) * 2;
            size_t gof = (size_t)(n0 + row) * ldK + k0 + c * 8;
            cp_async16(st + OFF_BH * 2 + dof, bh + gof);
            cp_async16(st + OFF_BL * 2 + dof, bl + gof);
        }
        cp_commit();
    };

    float acc[2][4][4];
    #pragma unroll
    for (int mi = 0; mi < 2; mi++)
        #pragma unroll
        for (int ni = 0; ni < 4; ni++)
            #pragma unroll
            for (int j = 0; j < 4; j++) acc[mi][ni][j] = 0.f;

    const int ar = lane & 15, ak = (lane >> 4) * 8;
    const uint32_t a_off = (uint32_t)((warpM * 32 + ar) * KS2 + ak) * 2;
    const int nr = (lane & 7) + ((lane >> 4) * 8);
    const int bk = ((lane >> 3) & 1) * 8;
    const uint32_t b_off = (uint32_t)((warpN * 32 + nr) * KS2 + bk) * 2;

    #pragma unroll
    for (int s = 0; s < STAGES - 1; s++) issue(s, s);

    for (int kt = 0; kt < nk; ++kt) {
        cp_wait<STAGES - 2>();
        __syncthreads();
        if (kt + STAGES - 1 < nk) issue(kt + STAGES - 1, (kt + STAGES - 1) % STAGES);

        const uint32_t st = sbase + (kt % STAGES) * (STAGE_H * 2);
        const uint32_t aA = st + a_off;
        const uint32_t aB = st + OFF_BH * 2 + b_off;

        #pragma unroll
        for (int ks = 0; ks < 4; ks++) {      // 4 k16 slices per BK=64 tile
            const uint32_t ko = ks * 32;       // 16 halves = 32 bytes
            uint32_t ah_[2][4], al_[2][4], bh_[2][4], bl_[2][4];
            #pragma unroll
            for (int mi = 0; mi < 2; mi++) {
                ldmx4(ah_[mi], aA + mi * (16 * KS2 * 2) + ko);
                ldmx4(al_[mi], aA + OFF_AL * 2 + mi * (16 * KS2 * 2) + ko);
            }
            #pragma unroll
            for (int np = 0; np < 2; np++) {
                ldmx4(bh_[np], aB + np * (16 * KS2 * 2) + ko);
                ldmx4(bl_[np], aB + (OFF_BL - OFF_BH) * 2 + np * (16 * KS2 * 2) + ko);
            }
            #pragma unroll
            for (int mi = 0; mi < 2; mi++)
                #pragma unroll
                for (int ni = 0; ni < 4; ni++) {
                    const int np = ni >> 1, jo = (ni & 1) * 2;
                    mma_bf16(acc[mi][ni], ah_[mi], &bh_[np][jo]);
                    mma_bf16(acc[mi][ni], ah_[mi], &bl_[np][jo]);
                    mma_bf16(acc[mi][ni], al_[mi], &bh_[np][jo]);
                }
        }
    }
    cp_wait<0>();

    // epilogue
    const size_t obase = (SPLITK ? (size_t)split * sPart : 0) + (size_t)batch * sC;
    #pragma unroll
    for (int mi = 0; mi < 2; mi++) {
        const int rbase = m0 + warpM * 32 + mi * 16 + gid;
        #pragma unroll
        for (int ni = 0; ni < 4; ni++) {
            const int col = n0 + warpN * 32 + ni * 8 + 2 * tg;
            float* c = acc[mi][ni];
            float b0 = 0.f, b1 = 0.f;
            if (BIAS) { b0 = bias[col]; b1 = bias[col + 1]; }
            #pragma unroll
            for (int h2 = 0; h2 < 2; h2++) {
                const int row = rbase + 8 * h2;
                float v0 = c[2 * h2 + 0] + b0;
                float v1 = c[2 * h2 + 1] + b1;
                if (RELU) { v0 = fmaxf(v0, 0.f); v1 = fmaxf(v1, 0.f); }
                const size_t o = obase + (size_t)row * N + col;
                if (SPLITK || WF32)
                    *reinterpret_cast<float2*>(Cf + o) = make_float2(v0, v1);
                if (WSPL || WT) {
                    bf16 h0_, l0_, h1_, l1_;
                    split2(v0, h0_, l0_); split2(v1, h1_, l1_);
                    if (WSPL) {
                        *reinterpret_cast<__nv_bfloat162*>(Ch + o) = __nv_bfloat162(h0_, h1_);
                        *reinterpret_cast<__nv_bfloat162*>(Cl + o) = __nv_bfloat162(l0_, l1_);
                    }
                    if (WT) {
                        const int bb_ = row >> 11, nn_ = row & 2047;
                        const size_t ot = (size_t)bb_ * (Dd * (size_t)Nn)
                                        + (size_t)col * Nn + nn_;
                        Th[ot] = h0_;      Tl[ot] = l0_;
                        Th[ot + Nn] = h1_; Tl[ot + Nn] = l1_;
                    }
                }
            }
        }
    }
}

// ---------------- launch --------------------------------------------------------
extern "C" void kernel_launch(void* const* d_in, const int* in_sizes, int n_in,
                              void* d_out, int out_size)
{
    (void)in_sizes; (void)n_in; (void)out_size;
    const float* x      = (const float*)d_in[0];
    const float* adj    = (const float*)d_in[1];
    const float* W_mlp2 = (const float*)d_in[2];
    const float* b_mlp2 = (const float*)d_in[3];
    const float* Wr[3]  = {(const float*)d_in[4], (const float*)d_in[7], (const float*)d_in[10]};
    const float* Wo[3]  = {(const float*)d_in[5], (const float*)d_in[8], (const float*)d_in[11]};
    const float* bs[3]  = {(const float*)d_in[6], (const float*)d_in[9], (const float*)d_in[12]};
    const float* W_mlp1 = (const float*)d_in[13];
    const float* b_mlp1 = (const float*)d_in[14];
    float* out = (float*)d_out;

    bf16 *h0h, *h0l, *h1h, *h1l, *aggh, *aggl, *hTh, *hTl;
    bf16 *xh, *xl, *W2h, *W2l, *W1h, *W1l, *Wrh, *Wrl, *Woh, *Wol, *adjh, *adjl;
    float* part;
    cudaGetSymbolAddress((void**)&h0h,  g_h0h); cudaGetSymbolAddress((void**)&h0l, g_h0l);
    cudaGetSymbolAddress((void**)&h1h,  g_h1h); cudaGetSymbolAddress((void**)&h1l, g_h1l);
    cudaGetSymbolAddress((void**)&aggh, g_aggh); cudaGetSymbolAddress((void**)&aggl, g_aggl);
    cudaGetSymbolAddress((void**)&hTh,  g_hTh); cudaGetSymbolAddress((void**)&hTl, g_hTl);
    cudaGetSymbolAddress((void**)&xh,   g_xh);  cudaGetSymbolAddress((void**)&xl,  g_xl);
    cudaGetSymbolAddress((void**)&W2h,  g_W2h); cudaGetSymbolAddress((void**)&W2l, g_W2l);
    cudaGetSymbolAddress((void**)&W1h,  g_W1h); cudaGetSymbolAddress((void**)&W1l, g_W1l);
    cudaGetSymbolAddress((void**)&Wrh,  g_Wrh); cudaGetSymbolAddress((void**)&Wrl, g_Wrl);
    cudaGetSymbolAddress((void**)&Woh,  g_Woh); cudaGetSymbolAddress((void**)&Wol, g_Wol);
    cudaGetSymbolAddress((void**)&adjh, g_adjh); cudaGetSymbolAddress((void**)&adjl, g_adjl);
    cudaGetSymbolAddress((void**)&part, g_part);
    const size_t sPart = (size_t)MT * Dd;
    float *p0 = part, *p1 = part + sPart, *p2 = part + 2 * sPart, *p3 = part + 3 * sPart;

    cudaFuncSetAttribute(gemm_bf<false, false, false, false, false, false, true >,
                         cudaFuncAttributeMaxDynamicSharedMemorySize, GEMM_SMEM);
    cudaFuncSetAttribute(gemm_bf<true,  true,  true,  false, true,  true,  false>,
                         cudaFuncAttributeMaxDynamicSharedMemorySize, GEMM_SMEM);
    cudaFuncSetAttribute(gemm_bf<true,  false, true,  false, true,  false, false>,
                         cudaFuncAttributeMaxDynamicSharedMemorySize, GEMM_SMEM);
    cudaFuncSetAttribute(gemm_bf<false, false, true,  true,  false, false, false>,
                         cudaFuncAttributeMaxDynamicSharedMemorySize, GEMM_SMEM);

    const size_t sHD = (size_t)Nn * Dd;

    // preprocessing
    adj_fused<<<Nn, 256>>>(adj);
    x_split_kernel<<<(MT * LD_ / 2) / 256, 256>>>((const float2*)x);
    wtrans_all<<<480, dim3(32, 8)>>>(W_mlp2, W_mlp1, Wr[0], Wo[0], Wr[1], Wo[1], Wr[2], Wo[2]);

    // mlp2 split-K 2: partials = x @ W_mlp2; grid 256  (kLen 768, 12 tiles)
    gemm_bf<false, false, false, false, false, false, true>
        <<<dim3(Dd / BN, MT / BM, 2), 256, GEMM_SMEM>>>(
        xh, xl, W2h, W2l, nullptr, nullptr, nullptr, nullptr,
        nullptr, part, nullptr, nullptr, nullptr, nullptr,
        Dd, LD_, LD_ / 2, 0, 0, 0, 0, 0, sPart);
    reduce_k<true, true><<<(MT * Dd / 2) / 256, 256>>>(
        (const float2*)p0, (const float2*)p1, b_mlp2, h0h, h0l, hTh, hTl);

    bf16* hinh = h0h; bf16* hinl = h0l;
    bf16* houth = h1h; bf16* houtl = h1l;
    for (int l = 0; l < 3; l++) {
        // agg partials = adjn @ hin (split-K 4 per batch; grid 512; kLen 512, 8 tiles)
        gemm_bf<false, false, false, false, false, false, true>
            <<<dim3(Dd / BN, Nn / BM, Bb * 4), 256, GEMM_SMEM>>>(
            adjh, adjl, hTh, hTl, nullptr, nullptr, nullptr, nullptr,
            nullptr, part, nullptr, nullptr, nullptr, nullptr,
            Dd, Nn, Nn / 4, 3, 2, 0, sHD, sHD, sPart);
        reduce_k4<<<(MT * Dd / 2) / 256, 256>>>(
            (const float2*)p0, (const float2*)p1, (const float2*)p2, (const float2*)p3,
            aggh, aggl);
        // h' = act(agg@Wr + hin@Wo + b)   grid 128 (dual K=128+128, 4 tiles)
        if (l < 2)
            gemm_bf<true, true, true, false, true, true, false>
                <<<dim3(Dd / BN, MT / BM, 1), 256, GEMM_SMEM>>>(
                aggh, aggl, Wrh + l * Dd * Dd, Wrl + l * Dd * Dd,
                hinh, hinl, Woh + l * Dd * Dd, Wol + l * Dd * Dd,
                bs[l], nullptr, houth, houtl, hTh, hTl,
                Dd, Dd, Dd, 0, 0, 0, 0, 0, 0);
        else
            gemm_bf<true, false, true, false, true, false, false>
                <<<dim3(Dd / BN, MT / BM, 1), 256, GEMM_SMEM>>>(
                aggh, aggl, Wrh + l * Dd * Dd, Wrl + l * Dd * Dd,
                hinh, hinl, Woh + l * Dd * Dd, Wol + l * Dd * Dd,
                bs[l], nullptr, houth, houtl, nullptr, nullptr,
                Dd, Dd, Dd, 0, 0, 0, 0, 0, 0);
        { bf16* t = hinh; hinh = houth; houth = t; }
        { bf16* t = hinl; hinl = houtl; houtl = t; }
    }

    // mlp1: out = hin @ W_mlp1 + b   (grid 1536; K=128, 2 tiles)
    gemm_bf<false, false, true, true, false, false, false>
        <<<dim3(LD_ / BN, MT / BM, 1), 256, GEMM_SMEM>>>(
        hinh, hinl, W1h, W1l, nullptr, nullptr, nullptr, nullptr,
        b_mlp1, out, nullptr, nullptr, nullptr, nullptr,
        LD_, Dd, Dd, 0, 0, 0, 0, 0, 0);
}

// round 13
// speedup vs baseline: 1.1331x; 1.0592x over previous
#include <cuda_runtime.h>
#include <cuda_bf16.h>
#include <cstdint>

#define Bb   4
#define Nn   2048
#define Ll   12
#define Dd   128
#define LD_  (Ll*Dd)      // 1536
#define MT   (Bb*Nn)      // 8192

typedef __nv_bfloat16 bf16;

// ---------------- scratch (device globals; no allocation) -------------------
__device__ bf16  g_h0h[MT * Dd];  __device__ bf16 g_h0l[MT * Dd];
__device__ bf16  g_h1h[MT * Dd];  __device__ bf16 g_h1l[MT * Dd];
__device__ bf16  g_aggh[MT * Dd]; __device__ bf16 g_aggl[MT * Dd];
__device__ bf16  g_hTh[Bb * Dd * Nn]; __device__ bf16 g_hTl[Bb * Dd * Nn];
__device__ bf16  g_adjh[Nn * Nn]; __device__ bf16 g_adjl[Nn * Nn];
__device__ bf16  g_W2h[Dd * LD_]; __device__ bf16 g_W2l[Dd * LD_];
__device__ bf16  g_W1h[LD_ * Dd]; __device__ bf16 g_W1l[LD_ * Dd];
__device__ bf16  g_Wrh[3][Dd * Dd]; __device__ bf16 g_Wrl[3][Dd * Dd];
__device__ bf16  g_Woh[3][Dd * Dd]; __device__ bf16 g_Wol[3][Dd * Dd];
__device__ float g_part[4][MT * Dd];   // split-K partials (16 MB)

// ---------------- helpers ----------------------------------------------------
__device__ __forceinline__ uint32_t smem_u32(const void* p) {
    uint32_t a;
    asm("{ .reg .u64 t; cvta.to.shared.u64 t, %1; cvt.u32.u64 %0, t; }"
        : "=r"(a) : "l"(p));
    return a;
}
__device__ __forceinline__ void cp_async16(uint32_t dst, const void* src) {
    asm volatile("cp.async.cg.shared.global [%0], [%1], 16;"
                 :: "r"(dst), "l"(src) : "memory");
}
__device__ __forceinline__ void cp_commit() {
    asm volatile("cp.async.commit_group;" ::: "memory");
}
template<int N_>
__device__ __forceinline__ void cp_wait() {
    asm volatile("cp.async.wait_group %0;" :: "n"(N_) : "memory");
}
__device__ __forceinline__ void ldmx4(uint32_t* r, uint32_t addr) {
    asm volatile("ldmatrix.sync.aligned.m8n8.x4.shared.b16 {%0,%1,%2,%3}, [%4];"
                 : "=r"(r[0]), "=r"(r[1]), "=r"(r[2]), "=r"(r[3]) : "r"(addr));
}
__device__ __forceinline__ void mma_bf16(float* c, const uint32_t* a, const uint32_t* b) {
    asm volatile(
        "mma.sync.aligned.m16n8k16.row.col.f32.bf16.bf16.f32 "
        "{%0,%1,%2,%3}, {%4,%5,%6,%7}, {%8,%9}, {%0,%1,%2,%3};"
        : "+f"(c[0]), "+f"(c[1]), "+f"(c[2]), "+f"(c[3])
        : "r"(a[0]), "r"(a[1]), "r"(a[2]), "r"(a[3]), "r"(b[0]), "r"(b[1]));
}
__device__ __forceinline__ void split2(float v, bf16& h, bf16& l) {
    h = __float2bfloat16(v);
    l = __float2bfloat16(v - __bfloat162float(h));
}

// ---------------- fused preprocessing ------------------------------------------
__global__ void adj_fused(const float* __restrict__ adj) {
    const int row = blockIdx.x;
    const int tid = threadIdx.x;
    const float* r = adj + (size_t)row * Nn;
    float v[8]; float s = 0.f;
    #pragma unroll
    for (int i = 0; i < 8; i++) { v[i] = r[tid + i * 256]; s += v[i]; }
    __shared__ float sm[8];
    #pragma unroll
    for (int o = 16; o > 0; o >>= 1) s += __shfl_down_sync(0xffffffffu, s, o);
    if ((tid & 31) == 0) sm[tid >> 5] = s;
    __syncthreads();
    __shared__ float rdeg;
    if (tid == 0) {
        float t = 0.f;
        #pragma unroll
        for (int i = 0; i < 8; i++) t += sm[i];
        rdeg = 1.0f / fmaxf(t, 1.0f);
    }
    __syncthreads();
    const float rd = rdeg;
    #pragma unroll
    for (int i = 0; i < 8; i++) {
        bf16 h, l;
        split2(v[i] * rd, h, l);
        size_t o = (size_t)row * Nn + tid + i * 256;
        g_adjh[o] = h; g_adjl[o] = l;
    }
}

__global__ void wtrans_all(const float* __restrict__ W2, const float* __restrict__ W1,
                           const float* __restrict__ Wr0, const float* __restrict__ Wo0,
                           const float* __restrict__ Wr1, const float* __restrict__ Wo1,
                           const float* __restrict__ Wr2, const float* __restrict__ Wo2)
{
    __shared__ float t[32][33];
    const int tb = blockIdx.x;
    const float* src; bf16* dh; bf16* dl; int R, C, tx, ty;
    if (tb < 192) {
        src = W2; dh = g_W2h; dl = g_W2l; R = LD_; C = Dd;
        ty = tb / 4; tx = tb % 4;
    } else if (tb < 384) {
        src = W1; dh = g_W1h; dl = g_W1l; R = Dd; C = LD_;
        int u = tb - 192; ty = u / 48; tx = u % 48;
    } else {
        int u = tb - 384; int l = u / 32; int v = u % 32;
        const float* wsrc[6] = {Wr0, Wo0, Wr1, Wo1, Wr2, Wo2};
        src = wsrc[l * 2 + (v < 16 ? 0 : 1)];
        if (v < 16) { dh = g_Wrh[l]; dl = g_Wrl[l]; }
        else        { dh = g_Woh[l]; dl = g_Wol[l]; }
        int w = v & 15; tx = w % 4; ty = w / 4; R = Dd; C = Dd;
    }
    const int c0 = tx * 32, r0 = ty * 32;
    const int x = threadIdx.x, y = threadIdx.y;
    #pragma unroll
    for (int i = 0; i < 32; i += 8)
        t[y + i][x] = src[(size_t)(r0 + y + i) * C + c0 + x];
    __syncthreads();
    #pragma unroll
    for (int i = 0; i < 32; i += 8) {
        bf16 h, l;
        split2(t[x][y + i], h, l);
        size_t o = (size_t)(c0 + y + i) * R + r0 + x;
        dh[o] = h; dl[o] = l;
    }
}

// ---------------- split-K reductions --------------------------------------------
template<bool BIAS, bool WT>
__global__ void reduce_k(const float2* __restrict__ p0, const float2* __restrict__ p1,
                         const float* __restrict__ bias,
                         bf16* __restrict__ Ch, bf16* __restrict__ Cl,
                         bf16* __restrict__ Th, bf16* __restrict__ Tl)
{
    const int idx = blockIdx.x * blockDim.x + threadIdx.x;   // over MT*Dd/2
    float2 a = p0[idx], b = p1[idx];
    float v0 = a.x + b.x, v1 = a.y + b.y;
    const int col = (2 * idx) & 127;
    if (BIAS) { v0 += bias[col]; v1 += bias[col + 1]; }
    bf16 h0, l0, h1, l1;
    split2(v0, h0, l0); split2(v1, h1, l1);
    *reinterpret_cast<__nv_bfloat162*>(Ch + 2 * idx) = __nv_bfloat162(h0, h1);
    *reinterpret_cast<__nv_bfloat162*>(Cl + 2 * idx) = __nv_bfloat162(l0, l1);
    if (WT) {
        const int row = (2 * idx) >> 7;
        const int bb_ = row >> 11, nn_ = row & 2047;
        const size_t ot = (size_t)bb_ * (Dd * (size_t)Nn) + (size_t)col * Nn + nn_;
        Th[ot] = h0;      Tl[ot] = l0;
        Th[ot + Nn] = h1; Tl[ot + Nn] = l1;
    }
}

__global__ void reduce_k4(const float2* __restrict__ p0, const float2* __restrict__ p1,
                          const float2* __restrict__ p2, const float2* __restrict__ p3,
                          bf16* __restrict__ Ch, bf16* __restrict__ Cl)
{
    const int idx = blockIdx.x * blockDim.x + threadIdx.x;   // over MT*Dd/2
    float2 a = p0[idx], b = p1[idx], c = p2[idx], d = p3[idx];
    float v0 = (a.x + b.x) + (c.x + d.x);
    float v1 = (a.y + b.y) + (c.y + d.y);
    bf16 h0, l0, h1, l1;
    split2(v0, h0, l0); split2(v1, h1, l1);
    *reinterpret_cast<__nv_bfloat162*>(Ch + 2 * idx) = __nv_bfloat162(h0, h1);
    *reinterpret_cast<__nv_bfloat162*>(Cl + 2 * idx) = __nv_bfloat162(l0, l1);
}

// ---------------- bf16x2 tensor-core GEMM -------------------------------------
// R12 body (BK=64, 2 stages). NEW: AF32 — A-side loads fp32 source directly,
// splits in registers, STS to hi/lo tiles (replaces the x_split pass).
#define STAGES 2
#define BM 64
#define BN 128
#define BK 64
#define KS2 72                              // 64 + 8 pad (halves)
#define OFF_AL (64 * KS2)                   // 4608 halves
#define OFF_BH (2 * 64 * KS2)               // 9216
#define OFF_BL (OFF_BH + 128 * KS2)         // 18432
#define STAGE_H (OFF_BL + 128 * KS2)        // 27648 halves = 55296 B
#define GEMM_SMEM (STAGES * STAGE_H * 2)    // 110592 B

template<bool DUAL, bool RELU, bool BIAS, bool WF32, bool WSPL, bool WT,
         bool SPLITK, bool AF32>
__global__ void __launch_bounds__(256, 2)
gemm_bf(const bf16* __restrict__ Ah, const bf16* __restrict__ Al,
        const float* __restrict__ Af,
        const bf16* __restrict__ Bh, const bf16* __restrict__ Bl,
        const bf16* __restrict__ A2h, const bf16* __restrict__ A2l,
        const bf16* __restrict__ B2h, const bf16* __restrict__ B2l,
        const float* __restrict__ bias,
        float* __restrict__ Cf, bf16* __restrict__ Ch, bf16* __restrict__ Cl,
        bf16* __restrict__ Th, bf16* __restrict__ Tl,
        int N, int ldK, int kLen, int zmask, int zshift,
        size_t sA, size_t sB, size_t sC, size_t sPart)
{
    extern __shared__ bf16 smem[];
    const uint32_t sbase = smem_u32(smem);
    const int tid = threadIdx.x;
    const int lane = tid & 31, wid = tid >> 5;
    const int warpM = wid & 1, warpN = wid >> 1;
    const int gid = lane >> 2, tg = lane & 3;

    const int m0 = blockIdx.y * BM, n0 = blockIdx.x * BN;
    int batch, split, kOff;
    if (SPLITK) { batch = blockIdx.z & zmask; split = blockIdx.z >> zshift;
                  kOff = split * kLen; }
    else        { batch = blockIdx.z; split = 0; kOff = 0; }

    const bf16* pAh = Ah + (size_t)batch * sA;
    const bf16* pAl = Al + (size_t)batch * sA;
    const bf16* pBh = Bh + (size_t)batch * sB;
    const bf16* pBl = Bl + (size_t)batch * sB;

    const int nk1 = kLen / BK;
    const int nk  = DUAL ? 2 * nk1 : nk1;

    auto issue = [&](int tile, int s) {
        const bf16 *bh, *bl; int k0;
        bool second = DUAL && (tile >= nk1);
        if (second) { bh = B2h; bl = B2l; k0 = (tile - nk1) * BK; }
        else        { bh = pBh; bl = pBl; k0 = kOff + tile * BK; }
        const uint32_t st = sbase + s * (STAGE_H * 2);

        // ---- A side ----
        if (AF32) {
            // fp32 source -> split in regs -> STS (64 rows x 64 cols)
            char* sp = reinterpret_cast<char*>(smem) + s * (STAGE_H * 2);
            #pragma unroll
            for (int i = 0; i < 2; i++) {
                int idx = tid + i * 256;
                int row = idx >> 3, c = idx & 7;
                size_t g = (size_t)(m0 + row) * ldK + k0 + c * 8;
                float4 u0 = *reinterpret_cast<const float4*>(Af + g);
                float4 u1 = *reinterpret_cast<const float4*>(Af + g + 4);
                float v[8] = {u0.x, u0.y, u0.z, u0.w, u1.x, u1.y, u1.z, u1.w};
                __nv_bfloat162 hh[4], ll[4];
                #pragma unroll
                for (int j = 0; j < 4; j++) {
                    bf16 h0_, l0_, h1_, l1_;
                    split2(v[2 * j], h0_, l0_); split2(v[2 * j + 1], h1_, l1_);
                    hh[j] = __nv_bfloat162(h0_, h1_); ll[j] = __nv_bfloat162(l0_, l1_);
                }
                uint32_t dof = (uint32_t)(row * KS2 + c * 8) * 2;
                *reinterpret_cast<uint4*>(sp + dof) = *reinterpret_cast<uint4*>(hh);
                *reinterpret_cast<uint4*>(sp + OFF_AL * 2 + dof) = *reinterpret_cast<uint4*>(ll);
            }
        } else {
            const bf16 *ah, *al;
            if (second) { ah = A2h; al = A2l; }
            else        { ah = pAh; al = pAl; }
            #pragma unroll
            for (int i = 0; i < 2; i++) {   // A: 64 rows x 8 chunks (hi + lo)
                int idx = tid + i * 256;
                int row = idx >> 3, c = idx & 7;
                uint32_t dof = (uint32_t)(row * KS2 + c * 8) * 2;
                size_t gof = (size_t)(m0 + row) * ldK + k0 + c * 8;
                cp_async16(st + dof,              ah + gof);
                cp_async16(st + OFF_AL * 2 + dof, al + gof);
            }
        }
        // ---- B side ----
        #pragma unroll
        for (int i = 0; i < 4; i++) {   // B: 128 rows x 8 chunks (hi + lo)
            int idx = tid + i * 256;
            int row = idx >> 3, c = idx & 7;
            uint32_t dof = (uint32_t)(row * KS2 + c * 8) * 2;
            size_t gof = (size_t)(n0 + row) * ldK + k0 + c * 8;
            cp_async16(st + OFF_BH * 2 + dof, bh + gof);
            cp_async16(st + OFF_BL * 2 + dof, bl + gof);
        }
        cp_commit();
    };

    float acc[2][4][4];
    #pragma unroll
    for (int mi = 0; mi < 2; mi++)
        #pragma unroll
        for (int ni = 0; ni < 4; ni++)
            #pragma unroll
            for (int j = 0; j < 4; j++) acc[mi][ni][j] = 0.f;

    const int ar = lane & 15, ak = (lane >> 4) * 8;
    const uint32_t a_off = (uint32_t)((warpM * 32 + ar) * KS2 + ak) * 2;
    const int nr = (lane & 7) + ((lane >> 4) * 8);
    const int bk = ((lane >> 3) & 1) * 8;
    const uint32_t b_off = (uint32_t)((warpN * 32 + nr) * KS2 + bk) * 2;

    #pragma unroll
    for (int s = 0; s < STAGES - 1; s++) issue(s, s);

    for (int kt = 0; kt < nk; ++kt) {
        cp_wait<STAGES - 2>();
        __syncthreads();
        if (kt + STAGES - 1 < nk) issue(kt + STAGES - 1, (kt + STAGES - 1) % STAGES);

        const uint32_t st = sbase + (kt % STAGES) * (STAGE_H * 2);
        const uint32_t aA = st + a_off;
        const uint32_t aB = st + OFF_BH * 2 + b_off;

        #pragma unroll
        for (int ks = 0; ks < 4; ks++) {      // 4 k16 slices per BK=64 tile
            const uint32_t ko = ks * 32;
            uint32_t ah_[2][4], al_[2][4], bh_[2][4], bl_[2][4];
            #pragma unroll
            for (int mi = 0; mi < 2; mi++) {
                ldmx4(ah_[mi], aA + mi * (16 * KS2 * 2) + ko);
                ldmx4(al_[mi], aA + OFF_AL * 2 + mi * (16 * KS2 * 2) + ko);
            }
            #pragma unroll
            for (int np = 0; np < 2; np++) {
                ldmx4(bh_[np], aB + np * (16 * KS2 * 2) + ko);
                ldmx4(bl_[np], aB + (OFF_BL - OFF_BH) * 2 + np * (16 * KS2 * 2) + ko);
            }
            #pragma unroll
            for (int mi = 0; mi < 2; mi++)
                #pragma unroll
                for (int ni = 0; ni < 4; ni++) {
                    const int np = ni >> 1, jo = (ni & 1) * 2;
                    mma_bf16(acc[mi][ni], ah_[mi], &bh_[np][jo]);
                    mma_bf16(acc[mi][ni], ah_[mi], &bl_[np][jo]);
                    mma_bf16(acc[mi][ni], al_[mi], &bh_[np][jo]);
                }
        }
    }
    cp_wait<0>();

    // epilogue
    const size_t obase = (SPLITK ? (size_t)split * sPart : 0) + (size_t)batch * sC;
    #pragma unroll
    for (int mi = 0; mi < 2; mi++) {
        const int rbase = m0 + warpM * 32 + mi * 16 + gid;
        #pragma unroll
        for (int ni = 0; ni < 4; ni++) {
            const int col = n0 + warpN * 32 + ni * 8 + 2 * tg;
            float* c = acc[mi][ni];
            float b0 = 0.f, b1 = 0.f;
            if (BIAS) { b0 = bias[col]; b1 = bias[col + 1]; }
            #pragma unroll
            for (int h2 = 0; h2 < 2; h2++) {
                const int row = rbase + 8 * h2;
                float v0 = c[2 * h2 + 0] + b0;
                float v1 = c[2 * h2 + 1] + b1;
                if (RELU) { v0 = fmaxf(v0, 0.f); v1 = fmaxf(v1, 0.f); }
                const size_t o = obase + (size_t)row * N + col;
                if (SPLITK || WF32)
                    *reinterpret_cast<float2*>(Cf + o) = make_float2(v0, v1);
                if (WSPL || WT) {
                    bf16 h0_, l0_, h1_, l1_;
                    split2(v0, h0_, l0_); split2(v1, h1_, l1_);
                    if (WSPL) {
                        *reinterpret_cast<__nv_bfloat162*>(Ch + o) = __nv_bfloat162(h0_, h1_);
                        *reinterpret_cast<__nv_bfloat162*>(Cl + o) = __nv_bfloat162(l0_, l1_);
                    }
                    if (WT) {
                        const int bb_ = row >> 11, nn_ = row & 2047;
                        const size_t ot = (size_t)bb_ * (Dd * (size_t)Nn)
                                        + (size_t)col * Nn + nn_;
                        Th[ot] = h0_;      Tl[ot] = l0_;
                        Th[ot + Nn] = h1_; Tl[ot + Nn] = l1_;
                    }
                }
            }
        }
    }
}

// ---------------- launch --------------------------------------------------------
extern "C" void kernel_launch(void* const* d_in, const int* in_sizes, int n_in,
                              void* d_out, int out_size)
{
    (void)in_sizes; (void)n_in; (void)out_size;
    const float* x      = (const float*)d_in[0];
    const float* adj    = (const float*)d_in[1];
    const float* W_mlp2 = (const float*)d_in[2];
    const float* b_mlp2 = (const float*)d_in[3];
    const float* Wr[3]  = {(const float*)d_in[4], (const float*)d_in[7], (const float*)d_in[10]};
    const float* Wo[3]  = {(const float*)d_in[5], (const float*)d_in[8], (const float*)d_in[11]};
    const float* bs[3]  = {(const float*)d_in[6], (const float*)d_in[9], (const float*)d_in[12]};
    const float* W_mlp1 = (const float*)d_in[13];
    const float* b_mlp1 = (const float*)d_in[14];
    float* out = (float*)d_out;

    bf16 *h0h, *h0l, *h1h, *h1l, *aggh, *aggl, *hTh, *hTl;
    bf16 *W2h, *W2l, *W1h, *W1l, *Wrh, *Wrl, *Woh, *Wol, *adjh, *adjl;
    float* part;
    cudaGetSymbolAddress((void**)&h0h,  g_h0h); cudaGetSymbolAddress((void**)&h0l, g_h0l);
    cudaGetSymbolAddress((void**)&h1h,  g_h1h); cudaGetSymbolAddress((void**)&h1l, g_h1l);
    cudaGetSymbolAddress((void**)&aggh, g_aggh); cudaGetSymbolAddress((void**)&aggl, g_aggl);
    cudaGetSymbolAddress((void**)&hTh,  g_hTh); cudaGetSymbolAddress((void**)&hTl, g_hTl);
    cudaGetSymbolAddress((void**)&W2h,  g_W2h); cudaGetSymbolAddress((void**)&W2l, g_W2l);
    cudaGetSymbolAddress((void**)&W1h,  g_W1h); cudaGetSymbolAddress((void**)&W1l, g_W1l);
    cudaGetSymbolAddress((void**)&Wrh,  g_Wrh); cudaGetSymbolAddress((void**)&Wrl, g_Wrl);
    cudaGetSymbolAddress((void**)&Woh,  g_Woh); cudaGetSymbolAddress((void**)&Wol, g_Wol);
    cudaGetSymbolAddress((void**)&adjh, g_adjh); cudaGetSymbolAddress((void**)&adjl, g_adjl);
    cudaGetSymbolAddress((void**)&part, g_part);
    const size_t sPart = (size_t)MT * Dd;
    float *p0 = part, *p1 = part + sPart, *p2 = part + 2 * sPart, *p3 = part + 3 * sPart;

    cudaFuncSetAttribute(gemm_bf<false, false, false, false, false, false, true,  true >,
                         cudaFuncAttributeMaxDynamicSharedMemorySize, GEMM_SMEM);
    cudaFuncSetAttribute(gemm_bf<false, false, false, false, false, false, true,  false>,
                         cudaFuncAttributeMaxDynamicSharedMemorySize, GEMM_SMEM);
    cudaFuncSetAttribute(gemm_bf<true,  true,  true,  false, true,  true,  false, false>,
                         cudaFuncAttributeMaxDynamicSharedMemorySize, GEMM_SMEM);
    cudaFuncSetAttribute(gemm_bf<true,  false, true,  false, true,  false, false, false>,
                         cudaFuncAttributeMaxDynamicSharedMemorySize, GEMM_SMEM);
    cudaFuncSetAttribute(gemm_bf<false, false, true,  true,  false, false, false, false>,
                         cudaFuncAttributeMaxDynamicSharedMemorySize, GEMM_SMEM);

    const size_t sHD = (size_t)Nn * Dd;

    // preprocessing (x_split eliminated — fused into mlp2 A-loader)
    adj_fused<<<Nn, 256>>>(adj);
    wtrans_all<<<480, dim3(32, 8)>>>(W_mlp2, W_mlp1, Wr[0], Wo[0], Wr[1], Wo[1], Wr[2], Wo[2]);

    // mlp2 split-K 2 (AF32 A-loader reads x fp32 directly): grid 256
    gemm_bf<false, false, false, false, false, false, true, true>
        <<<dim3(Dd / BN, MT / BM, 2), 256, GEMM_SMEM>>>(
        nullptr, nullptr, x, W2h, W2l, nullptr, nullptr, nullptr, nullptr,
        nullptr, part, nullptr, nullptr, nullptr, nullptr,
        Dd, LD_, LD_ / 2, 0, 0, 0, 0, 0, sPart);
    reduce_k<true, true><<<(MT * Dd / 2) / 256, 256>>>(
        (const float2*)p0, (const float2*)p1, b_mlp2, h0h, h0l, hTh, hTl);

    bf16* hinh = h0h; bf16* hinl = h0l;
    bf16* houth = h1h; bf16* houtl = h1l;
    for (int l = 0; l < 3; l++) {
        // agg partials = adjn @ hin (split-K 4 per batch; grid 512)
        gemm_bf<false, false, false, false, false, false, true, false>
            <<<dim3(Dd / BN, Nn / BM, Bb * 4), 256, GEMM_SMEM>>>(
            adjh, adjl, nullptr, hTh, hTl, nullptr, nullptr, nullptr, nullptr,
            nullptr, part, nullptr, nullptr, nullptr, nullptr,
            Dd, Nn, Nn / 4, 3, 2, 0, sHD, sHD, sPart);
        reduce_k4<<<(MT * Dd / 2) / 256, 256>>>(
            (const float2*)p0, (const float2*)p1, (const float2*)p2, (const float2*)p3,
            aggh, aggl);
        // h' = act(agg@Wr + hin@Wo + b)   grid 128
        if (l < 2)
            gemm_bf<true, true, true, false, true, true, false, false>
                <<<dim3(Dd / BN, MT / BM, 1), 256, GEMM_SMEM>>>(
                aggh, aggl, nullptr, Wrh + l * Dd * Dd, Wrl + l * Dd * Dd,
                hinh, hinl, Woh + l * Dd * Dd, Wol + l * Dd * Dd,
                bs[l], nullptr, houth, houtl, hTh, hTl,
                Dd, Dd, Dd, 0, 0, 0, 0, 0, 0);
        else
            gemm_bf<true, false, true, false, true, false, false, false>
                <<<dim3(Dd / BN, MT / BM, 1), 256, GEMM_SMEM>>>(
                aggh, aggl, nullptr, Wrh + l * Dd * Dd, Wrl + l * Dd * Dd,
                hinh, hinl, Woh + l * Dd * Dd, Wol + l * Dd * Dd,
                bs[l], nullptr, houth, houtl, nullptr, nullptr,
                Dd, Dd, Dd, 0, 0, 0, 0, 0, 0);
        { bf16* t = hinh; hinh = houth; houth = t; }
        { bf16* t = hinl; hinl = houtl; houtl = t; }
    }

    // mlp1: out = hin @ W_mlp1 + b   (grid 1536)
    gemm_bf<false, false, true, true, false, false, false, false>
        <<<dim3(LD_ / BN, MT / BM, 1), 256, GEMM_SMEM>>>(
        hinh, hinl, nullptr, W1h, W1l, nullptr, nullptr, nullptr, nullptr,
        b_mlp1, out, nullptr, nullptr, nullptr, nullptr,
        LD_, Dd, Dd, 0, 0, 0, 0, 0, 0);
}

// round 14
// speedup vs baseline: 1.2149x; 1.0722x over previous
#include <cuda_runtime.h>
#include <cuda_bf16.h>
#include <cstdint>

#define Bb   4
#define Nn   2048
#define Ll   12
#define Dd   128
#define LD_  (Ll*Dd)      // 1536
#define MT   (Bb*Nn)      // 8192

typedef __nv_bfloat16 bf16;

// ---------------- scratch (device globals; no allocation) -------------------
__device__ bf16  g_h0h[MT * Dd];  __device__ bf16 g_h0l[MT * Dd];
__device__ bf16  g_h1h[MT * Dd];  __device__ bf16 g_h1l[MT * Dd];
__device__ bf16  g_aggh[MT * Dd]; __device__ bf16 g_aggl[MT * Dd];
__device__ bf16  g_hTh[Bb * Dd * Nn]; __device__ bf16 g_hTl[Bb * Dd * Nn];
__device__ bf16  g_adjh[Nn * Nn]; __device__ bf16 g_adjl[Nn * Nn];
__device__ bf16  g_W2h[Dd * LD_]; __device__ bf16 g_W2l[Dd * LD_];
__device__ bf16  g_W1h[LD_ * Dd]; __device__ bf16 g_W1l[LD_ * Dd];
__device__ bf16  g_Wrh[3][Dd * Dd]; __device__ bf16 g_Wrl[3][Dd * Dd];
__device__ bf16  g_Woh[3][Dd * Dd]; __device__ bf16 g_Wol[3][Dd * Dd];
__device__ float g_part[4][MT * Dd];   // split-K partials (16 MB)

// ---------------- helpers ----------------------------------------------------
__device__ __forceinline__ uint32_t smem_u32(const void* p) {
    uint32_t a;
    asm("{ .reg .u64 t; cvta.to.shared.u64 t, %1; cvt.u32.u64 %0, t; }"
        : "=r"(a) : "l"(p));
    return a;
}
__device__ __forceinline__ void cp_async16(uint32_t dst, const void* src) {
    asm volatile("cp.async.cg.shared.global [%0], [%1], 16;"
                 :: "r"(dst), "l"(src) : "memory");
}
__device__ __forceinline__ void cp_commit() {
    asm volatile("cp.async.commit_group;" ::: "memory");
}
template<int N_>
__device__ __forceinline__ void cp_wait() {
    asm volatile("cp.async.wait_group %0;" :: "n"(N_) : "memory");
}
__device__ __forceinline__ void ldmx4(uint32_t* r, uint32_t addr) {
    asm volatile("ldmatrix.sync.aligned.m8n8.x4.shared.b16 {%0,%1,%2,%3}, [%4];"
                 : "=r"(r[0]), "=r"(r[1]), "=r"(r[2]), "=r"(r[3]) : "r"(addr));
}
__device__ __forceinline__ void mma_bf16(float* c, const uint32_t* a, const uint32_t* b) {
    asm volatile(
        "mma.sync.aligned.m16n8k16.row.col.f32.bf16.bf16.f32 "
        "{%0,%1,%2,%3}, {%4,%5,%6,%7}, {%8,%9}, {%0,%1,%2,%3};"
        : "+f"(c[0]), "+f"(c[1]), "+f"(c[2]), "+f"(c[3])
        : "r"(a[0]), "r"(a[1]), "r"(a[2]), "r"(a[3]), "r"(b[0]), "r"(b[1]));
}
__device__ __forceinline__ void split2(float v, bf16& h, bf16& l) {
    h = __float2bfloat16(v);
    l = __float2bfloat16(v - __bfloat162float(h));
}

// ---------------- fused preprocessing ------------------------------------------
__global__ void adj_fused(const float* __restrict__ adj) {
    const int row = blockIdx.x;
    const int tid = threadIdx.x;
    const float* r = adj + (size_t)row * Nn;
    float v[8]; float s = 0.f;
    #pragma unroll
    for (int i = 0; i < 8; i++) { v[i] = r[tid + i * 256]; s += v[i]; }
    __shared__ float sm[8];
    #pragma unroll
    for (int o = 16; o > 0; o >>= 1) s += __shfl_down_sync(0xffffffffu, s, o);
    if ((tid & 31) == 0) sm[tid >> 5] = s;
    __syncthreads();
    __shared__ float rdeg;
    if (tid == 0) {
        float t = 0.f;
        #pragma unroll
        for (int i = 0; i < 8; i++) t += sm[i];
        rdeg = 1.0f / fmaxf(t, 1.0f);
    }
    __syncthreads();
    const float rd = rdeg;
    #pragma unroll
    for (int i = 0; i < 8; i++) {
        bf16 h, l;
        split2(v[i] * rd, h, l);
        size_t o = (size_t)row * Nn + tid + i * 256;
        g_adjh[o] = h; g_adjl[o] = l;
    }
}

__global__ void wtrans_all(const float* __restrict__ W2, const float* __restrict__ W1,
                           const float* __restrict__ Wr0, const float* __restrict__ Wo0,
                           const float* __restrict__ Wr1, const float* __restrict__ Wo1,
                           const float* __restrict__ Wr2, const float* __restrict__ Wo2)
{
    __shared__ float t[32][33];
    const int tb = blockIdx.x;
    const float* src; bf16* dh; bf16* dl; int R, C, tx, ty;
    if (tb < 192) {
        src = W2; dh = g_W2h; dl = g_W2l; R = LD_; C = Dd;
        ty = tb / 4; tx = tb % 4;
    } else if (tb < 384) {
        src = W1; dh = g_W1h; dl = g_W1l; R = Dd; C = LD_;
        int u = tb - 192; ty = u / 48; tx = u % 48;
    } else {
        int u = tb - 384; int l = u / 32; int v = u % 32;
        const float* wsrc[6] = {Wr0, Wo0, Wr1, Wo1, Wr2, Wo2};
        src = wsrc[l * 2 + (v < 16 ? 0 : 1)];
        if (v < 16) { dh = g_Wrh[l]; dl = g_Wrl[l]; }
        else        { dh = g_Woh[l]; dl = g_Wol[l]; }
        int w = v & 15; tx = w % 4; ty = w / 4; R = Dd; C = Dd;
    }
    const int c0 = tx * 32, r0 = ty * 32;
    const int x = threadIdx.x, y = threadIdx.y;
    #pragma unroll
    for (int i = 0; i < 32; i += 8)
        t[y + i][x] = src[(size_t)(r0 + y + i) * C + c0 + x];
    __syncthreads();
    #pragma unroll
    for (int i = 0; i < 32; i += 8) {
        bf16 h, l;
        split2(t[x][y + i], h, l);
        size_t o = (size_t)(c0 + y + i) * R + r0 + x;
        dh[o] = h; dl[o] = l;
    }
}

// ---------------- split-K reductions --------------------------------------------
// mlp2 reduce with COALESCED transposed output (32x32 smem tile).
// grid (Dd/32, MT/32), block (32, 8)
__global__ void reduce_wt(const float* __restrict__ p0, const float* __restrict__ p1,
                          const float* __restrict__ bias,
                          bf16* __restrict__ Ch, bf16* __restrict__ Cl,
                          bf16* __restrict__ Th, bf16* __restrict__ Tl)
{
    __shared__ float t[32][33];
    const int c0 = blockIdx.x * 32;     // col in Dd
    const int r0 = blockIdx.y * 32;     // row in MT (never crosses batch)
    const int x = threadIdx.x, y = threadIdx.y;
    const float bcol = bias[c0 + x];
    #pragma unroll
    for (int i = 0; i < 32; i += 8) {
        const int row = r0 + y + i;
        const size_t o = (size_t)row * Dd + c0 + x;
        float v = p0[o] + p1[o] + bcol;
        t[y + i][x] = v;
        bf16 h, l; split2(v, h, l);
        Ch[o] = h; Cl[o] = l;
    }
    __syncthreads();
    const int bb = r0 >> 11;
    const size_t tbase = (size_t)bb * (Dd * (size_t)Nn) + (r0 & 2047) + x;
    #pragma unroll
    for (int i = 0; i < 32; i += 8) {
        const int col = c0 + y + i;
        bf16 h, l; split2(t[x][y + i], h, l);
        const size_t ot = tbase + (size_t)col * Nn;
        Th[ot] = h; Tl[ot] = l;
    }
}

__global__ void reduce_k4(const float2* __restrict__ p0, const float2* __restrict__ p1,
                          const float2* __restrict__ p2, const float2* __restrict__ p3,
                          bf16* __restrict__ Ch, bf16* __restrict__ Cl)
{
    const int idx = blockIdx.x * blockDim.x + threadIdx.x;   // over MT*Dd/2
    float2 a = p0[idx], b = p1[idx], c = p2[idx], d = p3[idx];
    float v0 = (a.x + b.x) + (c.x + d.x);
    float v1 = (a.y + b.y) + (c.y + d.y);
    bf16 h0, l0, h1, l1;
    split2(v0, h0, l0); split2(v1, h1, l1);
    *reinterpret_cast<__nv_bfloat162*>(Ch + 2 * idx) = __nv_bfloat162(h0, h1);
    *reinterpret_cast<__nv_bfloat162*>(Cl + 2 * idx) = __nv_bfloat162(l0, l1);
}

// ---------------- bf16x2 tensor-core GEMM -------------------------------------
// R13 body (BK=64, 2 stages, AF32). NEW: WT epilogue stages split values in
// smem (stride-72 transpose buffer reusing pipeline smem) and writes hT with
// coalesced 16B chunks instead of scattered 2B stores.
#define STAGES 2
#define BM 64
#define BN 128
#define BK 64
#define KS2 72
#define OFF_AL (64 * KS2)
#define OFF_BH (2 * 64 * KS2)
#define OFF_BL (OFF_BH + 128 * KS2)
#define STAGE_H (OFF_BL + 128 * KS2)
#define GEMM_SMEM (STAGES * STAGE_H * 2)    // 110592 B
#define TS 72                                // transpose staging stride (halves)

template<bool DUAL, bool RELU, bool BIAS, bool WF32, bool WSPL, bool WT,
         bool SPLITK, bool AF32>
__global__ void __launch_bounds__(256, 2)
gemm_bf(const bf16* __restrict__ Ah, const bf16* __restrict__ Al,
        const float* __restrict__ Af,
        const bf16* __restrict__ Bh, const bf16* __restrict__ Bl,
        const bf16* __restrict__ A2h, const bf16* __restrict__ A2l,
        const bf16* __restrict__ B2h, const bf16* __restrict__ B2l,
        const float* __restrict__ bias,
        float* __restrict__ Cf, bf16* __restrict__ Ch, bf16* __restrict__ Cl,
        bf16* __restrict__ Th, bf16* __restrict__ Tl,
        int N, int ldK, int kLen, int zmask, int zshift,
        size_t sA, size_t sB, size_t sC, size_t sPart)
{
    extern __shared__ bf16 smem[];
    const uint32_t sbase = smem_u32(smem);
    const int tid = threadIdx.x;
    const int lane = tid & 31, wid = tid >> 5;
    const int warpM = wid & 1, warpN = wid >> 1;
    const int gid = lane >> 2, tg = lane & 3;

    const int m0 = blockIdx.y * BM, n0 = blockIdx.x * BN;
    int batch, split, kOff;
    if (SPLITK) { batch = blockIdx.z & zmask; split = blockIdx.z >> zshift;
                  kOff = split * kLen; }
    else        { batch = blockIdx.z; split = 0; kOff = 0; }

    const bf16* pAh = Ah + (size_t)batch * sA;
    const bf16* pAl = Al + (size_t)batch * sA;
    const bf16* pBh = Bh + (size_t)batch * sB;
    const bf16* pBl = Bl + (size_t)batch * sB;

    const int nk1 = kLen / BK;
    const int nk  = DUAL ? 2 * nk1 : nk1;

    auto issue = [&](int tile, int s) {
        const bf16 *bh, *bl; int k0;
        bool second = DUAL && (tile >= nk1);
        if (second) { bh = B2h; bl = B2l; k0 = (tile - nk1) * BK; }
        else        { bh = pBh; bl = pBl; k0 = kOff + tile * BK; }
        const uint32_t st = sbase + s * (STAGE_H * 2);

        if (AF32) {
            char* sp = reinterpret_cast<char*>(smem) + s * (STAGE_H * 2);
            #pragma unroll
            for (int i = 0; i < 2; i++) {
                int idx = tid + i * 256;
                int row = idx >> 3, c = idx & 7;
                size_t g = (size_t)(m0 + row) * ldK + k0 + c * 8;
                float4 u0 = *reinterpret_cast<const float4*>(Af + g);
                float4 u1 = *reinterpret_cast<const float4*>(Af + g + 4);
                float v[8] = {u0.x, u0.y, u0.z, u0.w, u1.x, u1.y, u1.z, u1.w};
                __nv_bfloat162 hh[4], ll[4];
                #pragma unroll
                for (int j = 0; j < 4; j++) {
                    bf16 h0_, l0_, h1_, l1_;
                    split2(v[2 * j], h0_, l0_); split2(v[2 * j + 1], h1_, l1_);
                    hh[j] = __nv_bfloat162(h0_, h1_); ll[j] = __nv_bfloat162(l0_, l1_);
                }
                uint32_t dof = (uint32_t)(row * KS2 + c * 8) * 2;
                *reinterpret_cast<uint4*>(sp + dof) = *reinterpret_cast<uint4*>(hh);
                *reinterpret_cast<uint4*>(sp + OFF_AL * 2 + dof) = *reinterpret_cast<uint4*>(ll);
            }
        } else {
            const bf16 *ah, *al;
            if (second) { ah = A2h; al = A2l; }
            else        { ah = pAh; al = pAl; }
            #pragma unroll
            for (int i = 0; i < 2; i++) {
                int idx = tid + i * 256;
                int row = idx >> 3, c = idx & 7;
                uint32_t dof = (uint32_t)(row * KS2 + c * 8) * 2;
                size_t gof = (size_t)(m0 + row) * ldK + k0 + c * 8;
                cp_async16(st + dof,              ah + gof);
                cp_async16(st + OFF_AL * 2 + dof, al + gof);
            }
        }
        #pragma unroll
        for (int i = 0; i < 4; i++) {
            int idx = tid + i * 256;
            int row = idx >> 3, c = idx & 7;
            uint32_t dof = (uint32_t)(row * KS2 + c * 8) * 2;
            size_t gof = (size_t)(n0 + row) * ldK + k0 + c * 8;
            cp_async16(st + OFF_BH * 2 + dof, bh + gof);
            cp_async16(st + OFF_BL * 2 + dof, bl + gof);
        }
        cp_commit();
    };

    float acc[2][4][4];
    #pragma unroll
    for (int mi = 0; mi < 2; mi++)
        #pragma unroll
        for (int ni = 0; ni < 4; ni++)
            #pragma unroll
            for (int j = 0; j < 4; j++) acc[mi][ni][j] = 0.f;

    const int ar = lane & 15, ak = (lane >> 4) * 8;
    const uint32_t a_off = (uint32_t)((warpM * 32 + ar) * KS2 + ak) * 2;
    const int nr = (lane & 7) + ((lane >> 4) * 8);
    const int bk = ((lane >> 3) & 1) * 8;
    const uint32_t b_off = (uint32_t)((warpN * 32 + nr) * KS2 + bk) * 2;

    #pragma unroll
    for (int s = 0; s < STAGES - 1; s++) issue(s, s);

    for (int kt = 0; kt < nk; ++kt) {
        cp_wait<STAGES - 2>();
        __syncthreads();
        if (kt + STAGES - 1 < nk) issue(kt + STAGES - 1, (kt + STAGES - 1) % STAGES);

        const uint32_t st = sbase + (kt % STAGES) * (STAGE_H * 2);
        const uint32_t aA = st + a_off;
        const uint32_t aB = st + OFF_BH * 2 + b_off;

        #pragma unroll
        for (int ks = 0; ks < 4; ks++) {
            const uint32_t ko = ks * 32;
            uint32_t ah_[2][4], al_[2][4], bh_[2][4], bl_[2][4];
            #pragma unroll
            for (int mi = 0; mi < 2; mi++) {
                ldmx4(ah_[mi], aA + mi * (16 * KS2 * 2) + ko);
                ldmx4(al_[mi], aA + OFF_AL * 2 + mi * (16 * KS2 * 2) + ko);
            }
            #pragma unroll
            for (int np = 0; np < 2; np++) {
                ldmx4(bh_[np], aB + np * (16 * KS2 * 2) + ko);
                ldmx4(bl_[np], aB + (OFF_BL - OFF_BH) * 2 + np * (16 * KS2 * 2) + ko);
            }
            #pragma unroll
            for (int mi = 0; mi < 2; mi++)
                #pragma unroll
                for (int ni = 0; ni < 4; ni++) {
                    const int np = ni >> 1, jo = (ni & 1) * 2;
                    mma_bf16(acc[mi][ni], ah_[mi], &bh_[np][jo]);
                    mma_bf16(acc[mi][ni], ah_[mi], &bl_[np][jo]);
                    mma_bf16(acc[mi][ni], al_[mi], &bh_[np][jo]);
                }
        }
    }
    cp_wait<0>();
    // WT: smem is reused as a transpose staging buffer — wait for all warps'
    // ldmatrix reads of the final tile before overwriting.
    bf16* thbuf = smem;
    bf16* tlbuf = smem + 128 * TS;
    if (WT) __syncthreads();

    // epilogue
    const size_t obase = (SPLITK ? (size_t)split * sPart : 0) + (size_t)batch * sC;
    #pragma unroll
    for (int mi = 0; mi < 2; mi++) {
        const int rl = warpM * 32 + mi * 16 + gid;   // row within tile
        #pragma unroll
        for (int ni = 0; ni < 4; ni++) {
            const int cl = warpN * 32 + ni * 8 + 2 * tg;  // col within tile
            const int col = n0 + cl;
            float* c = acc[mi][ni];
            float b0 = 0.f, b1 = 0.f;
            if (BIAS) { b0 = bias[col]; b1 = bias[col + 1]; }
            #pragma unroll
            for (int h2 = 0; h2 < 2; h2++) {
                const int row = m0 + rl + 8 * h2;
                float v0 = c[2 * h2 + 0] + b0;
                float v1 = c[2 * h2 + 1] + b1;
                if (RELU) { v0 = fmaxf(v0, 0.f); v1 = fmaxf(v1, 0.f); }
                const size_t o = obase + (size_t)row * N + col;
                if (SPLITK || WF32)
                    *reinterpret_cast<float2*>(Cf + o) = make_float2(v0, v1);
                if (WSPL || WT) {
                    bf16 h0_, l0_, h1_, l1_;
                    split2(v0, h0_, l0_); split2(v1, h1_, l1_);
                    if (WSPL) {
                        *reinterpret_cast<__nv_bfloat162*>(Ch + o) = __nv_bfloat162(h0_, h1_);
                        *reinterpret_cast<__nv_bfloat162*>(Cl + o) = __nv_bfloat162(l0_, l1_);
                    }
                    if (WT) {   // stage into smem transpose buffers
                        const int r2 = rl + 8 * h2;
                        thbuf[cl * TS + r2] = h0_;       tlbuf[cl * TS + r2] = l0_;
                        thbuf[(cl + 1) * TS + r2] = h1_; tlbuf[(cl + 1) * TS + r2] = l1_;
                    }
                }
            }
        }
    }
    if (WT) {
        __syncthreads();
        const int bb_ = m0 >> 11;
        const size_t tb = (size_t)bb_ * (Dd * (size_t)Nn) + (m0 & 2047);
        #pragma unroll
        for (int it = 0; it < 4; it++) {        // 128 cols x 8 chunks / 256 thr
            const int idx = tid + it * 256;
            const int colr = idx >> 3, ch = idx & 7;
            uint4 vh = *reinterpret_cast<uint4*>(thbuf + colr * TS + ch * 8);
            uint4 vl = *reinterpret_cast<uint4*>(tlbuf + colr * TS + ch * 8);
            const size_t ot = tb + (size_t)(n0 + colr) * Nn + ch * 8;
            *reinterpret_cast<uint4*>(Th + ot) = vh;
            *reinterpret_cast<uint4*>(Tl + ot) = vl;
        }
    }
}

// ---------------- launch --------------------------------------------------------
extern "C" void kernel_launch(void* const* d_in, const int* in_sizes, int n_in,
                              void* d_out, int out_size)
{
    (void)in_sizes; (void)n_in; (void)out_size;
    const float* x      = (const float*)d_in[0];
    const float* adj    = (const float*)d_in[1];
    const float* W_mlp2 = (const float*)d_in[2];
    const float* b_mlp2 = (const float*)d_in[3];
    const float* Wr[3]  = {(const float*)d_in[4], (const float*)d_in[7], (const float*)d_in[10]};
    const float* Wo[3]  = {(const float*)d_in[5], (const float*)d_in[8], (const float*)d_in[11]};
    const float* bs[3]  = {(const float*)d_in[6], (const float*)d_in[9], (const float*)d_in[12]};
    const float* W_mlp1 = (const float*)d_in[13];
    const float* b_mlp1 = (const float*)d_in[14];
    float* out = (float*)d_out;

    bf16 *h0h, *h0l, *h1h, *h1l, *aggh, *aggl, *hTh, *hTl;
    bf16 *W2h, *W2l, *W1h, *W1l, *Wrh, *Wrl, *Woh, *Wol, *adjh, *adjl;
    float* part;
    cudaGetSymbolAddress((void**)&h0h,  g_h0h); cudaGetSymbolAddress((void**)&h0l, g_h0l);
    cudaGetSymbolAddress((void**)&h1h,  g_h1h); cudaGetSymbolAddress((void**)&h1l, g_h1l);
    cudaGetSymbolAddress((void**)&aggh, g_aggh); cudaGetSymbolAddress((void**)&aggl, g_aggl);
    cudaGetSymbolAddress((void**)&hTh,  g_hTh); cudaGetSymbolAddress((void**)&hTl, g_hTl);
    cudaGetSymbolAddress((void**)&W2h,  g_W2h); cudaGetSymbolAddress((void**)&W2l, g_W2l);
    cudaGetSymbolAddress((void**)&W1h,  g_W1h); cudaGetSymbolAddress((void**)&W1l, g_W1l);
    cudaGetSymbolAddress((void**)&Wrh,  g_Wrh); cudaGetSymbolAddress((void**)&Wrl, g_Wrl);
    cudaGetSymbolAddress((void**)&Woh,  g_Woh); cudaGetSymbolAddress((void**)&Wol, g_Wol);
    cudaGetSymbolAddress((void**)&adjh, g_adjh); cudaGetSymbolAddress((void**)&adjl, g_adjl);
    cudaGetSymbolAddress((void**)&part, g_part);
    const size_t sPart = (size_t)MT * Dd;
    float *p0 = part, *p1 = part + sPart, *p2 = part + 2 * sPart, *p3 = part + 3 * sPart;

    cudaFuncSetAttribute(gemm_bf<false, false, false, false, false, false, true,  true >,
                         cudaFuncAttributeMaxDynamicSharedMemorySize, GEMM_SMEM);
    cudaFuncSetAttribute(gemm_bf<false, false, false, false, false, false, true,  false>,
                         cudaFuncAttributeMaxDynamicSharedMemorySize, GEMM_SMEM);
    cudaFuncSetAttribute(gemm_bf<true,  true,  true,  false, true,  true,  false, false>,
                         cudaFuncAttributeMaxDynamicSharedMemorySize, GEMM_SMEM);
    cudaFuncSetAttribute(gemm_bf<true,  false, true,  false, true,  false, false, false>,
                         cudaFuncAttributeMaxDynamicSharedMemorySize, GEMM_SMEM);
    cudaFuncSetAttribute(gemm_bf<false, false, true,  true,  false, false, false, false>,
                         cudaFuncAttributeMaxDynamicSharedMemorySize, GEMM_SMEM);

    const size_t sHD = (size_t)Nn * Dd;

    // preprocessing
    adj_fused<<<Nn, 256>>>(adj);
    wtrans_all<<<480, dim3(32, 8)>>>(W_mlp2, W_mlp1, Wr[0], Wo[0], Wr[1], Wo[1], Wr[2], Wo[2]);

    // mlp2 split-K 2 (AF32 loader reads x fp32 directly): grid 256
    gemm_bf<false, false, false, false, false, false, true, true>
        <<<dim3(Dd / BN, MT / BM, 2), 256, GEMM_SMEM>>>(
        nullptr, nullptr, x, W2h, W2l, nullptr, nullptr, nullptr, nullptr,
        nullptr, part, nullptr, nullptr, nullptr, nullptr,
        Dd, LD_, LD_ / 2, 0, 0, 0, 0, 0, sPart);
    // reduce + coalesced transposed hT emit
    reduce_wt<<<dim3(Dd / 32, MT / 32), dim3(32, 8)>>>(
        p0, p1, b_mlp2, h0h, h0l, hTh, hTl);

    bf16* hinh = h0h; bf16* hinl = h0l;
    bf16* houth = h1h; bf16* houtl = h1l;
    for (int l = 0; l < 3; l++) {
        // agg partials = adjn @ hin (split-K 4 per batch; grid 512)
        gemm_bf<false, false, false, false, false, false, true, false>
            <<<dim3(Dd / BN, Nn / BM, Bb * 4), 256, GEMM_SMEM>>>(
            adjh, adjl, nullptr, hTh, hTl, nullptr, nullptr, nullptr, nullptr,
            nullptr, part, nullptr, nullptr, nullptr, nullptr,
            Dd, Nn, Nn / 4, 3, 2, 0, sHD, sHD, sPart);
        reduce_k4<<<(MT * Dd / 2) / 256, 256>>>(
            (const float2*)p0, (const float2*)p1, (const float2*)p2, (const float2*)p3,
            aggh, aggl);
        // h' = act(agg@Wr + hin@Wo + b)   grid 128
        if (l < 2)
            gemm_bf<true, true, true, false, true, true, false, false>
                <<<dim3(Dd / BN, MT / BM, 1), 256, GEMM_SMEM>>>(
                aggh, aggl, nullptr, Wrh + l * Dd * Dd, Wrl + l * Dd * Dd,
                hinh, hinl, Woh + l * Dd * Dd, Wol + l * Dd * Dd,
                bs[l], nullptr, houth, houtl, hTh, hTl,
                Dd, Dd, Dd, 0, 0, 0, 0, 0, 0);
        else
            gemm_bf<true, false, true, false, true, false, false, false>
                <<<dim3(Dd / BN, MT / BM, 1), 256, GEMM_SMEM>>>(
                aggh, aggl, nullptr, Wrh + l * Dd * Dd, Wrl + l * Dd * Dd,
                hinh, hinl, Woh + l * Dd * Dd, Wol + l * Dd * Dd,
                bs[l], nullptr, houth, houtl, nullptr, nullptr,
                Dd, Dd, Dd, 0, 0, 0, 0, 0, 0);
        { bf16* t = hinh; hinh = houth; houth = t; }
        { bf16* t = hinl; hinl = houtl; houtl = t; }
    }

    // mlp1: out = hin @ W_mlp1 + b   (grid 1536)
    gemm_bf<false, false, true, true, false, false, false, false>
        <<<dim3(LD_ / BN, MT / BM, 1), 256, GEMM_SMEM>>>(
        hinh, hinl, nullptr, W1h, W1l, nullptr, nullptr, nullptr, nullptr,
        b_mlp1, out, nullptr, nullptr, nullptr, nullptr,
        LD_, Dd, Dd, 0, 0, 0, 0, 0, 0);
}

// round 15
// speedup vs baseline: 1.2330x; 1.0149x over previous
#include <cuda_runtime.h>
#include <cuda_bf16.h>
#include <cstdint>

#define Bb   4
#define Nn   2048
#define Ll   12
#define Dd   128
#define LD_  (Ll*Dd)      // 1536
#define MT   (Bb*Nn)      // 8192

typedef __nv_bfloat16 bf16;

// ---------------- scratch (device globals; no allocation) -------------------
__device__ bf16  g_h0h[MT * Dd];  __device__ bf16 g_h0l[MT * Dd];
__device__ bf16  g_h1h[MT * Dd];  __device__ bf16 g_h1l[MT * Dd];
__device__ bf16  g_hTh[Bb * Dd * Nn]; __device__ bf16 g_hTl[Bb * Dd * Nn];
__device__ bf16  g_adjh[Nn * Nn]; __device__ bf16 g_adjl[Nn * Nn];
__device__ bf16  g_W2h[Dd * LD_]; __device__ bf16 g_W2l[Dd * LD_];
__device__ bf16  g_W1h[LD_ * Dd]; __device__ bf16 g_W1l[LD_ * Dd];
__device__ bf16  g_Wrh[3][Dd * Dd]; __device__ bf16 g_Wrl[3][Dd * Dd];
__device__ bf16  g_Woh[3][Dd * Dd]; __device__ bf16 g_Wol[3][Dd * Dd];
__device__ float g_part[4][MT * Dd];   // split-K partials (16 MB)

// ---------------- helpers ----------------------------------------------------
__device__ __forceinline__ uint32_t smem_u32(const void* p) {
    uint32_t a;
    asm("{ .reg .u64 t; cvta.to.shared.u64 t, %1; cvt.u32.u64 %0, t; }"
        : "=r"(a) : "l"(p));
    return a;
}
__device__ __forceinline__ void cp_async16(uint32_t dst, const void* src) {
    asm volatile("cp.async.cg.shared.global [%0], [%1], 16;"
                 :: "r"(dst), "l"(src) : "memory");
}
__device__ __forceinline__ void cp_commit() {
    asm volatile("cp.async.commit_group;" ::: "memory");
}
template<int N_>
__device__ __forceinline__ void cp_wait() {
    asm volatile("cp.async.wait_group %0;" :: "n"(N_) : "memory");
}
__device__ __forceinline__ void ldmx4(uint32_t* r, uint32_t addr) {
    asm volatile("ldmatrix.sync.aligned.m8n8.x4.shared.b16 {%0,%1,%2,%3}, [%4];"
                 : "=r"(r[0]), "=r"(r[1]), "=r"(r[2]), "=r"(r[3]) : "r"(addr));
}
__device__ __forceinline__ void mma_bf16(float* c, const uint32_t* a, const uint32_t* b) {
    asm volatile(
        "mma.sync.aligned.m16n8k16.row.col.f32.bf16.bf16.f32 "
        "{%0,%1,%2,%3}, {%4,%5,%6,%7}, {%8,%9}, {%0,%1,%2,%3};"
        : "+f"(c[0]), "+f"(c[1]), "+f"(c[2]), "+f"(c[3])
        : "r"(a[0]), "r"(a[1]), "r"(a[2]), "r"(a[3]), "r"(b[0]), "r"(b[1]));
}
__device__ __forceinline__ void split2(float v, bf16& h, bf16& l) {
    h = __float2bfloat16(v);
    l = __float2bfloat16(v - __bfloat162float(h));
}

// ---------------- fused preprocessing ------------------------------------------
__global__ void adj_fused(const float* __restrict__ adj) {
    const int row = blockIdx.x;
    const int tid = threadIdx.x;
    const float* r = adj + (size_t)row * Nn;
    float v[8]; float s = 0.f;
    #pragma unroll
    for (int i = 0; i < 8; i++) { v[i] = r[tid + i * 256]; s += v[i]; }
    __shared__ float sm[8];
    #pragma unroll
    for (int o = 16; o > 0; o >>= 1) s += __shfl_down_sync(0xffffffffu, s, o);
    if ((tid & 31) == 0) sm[tid >> 5] = s;
    __syncthreads();
    __shared__ float rdeg;
    if (tid == 0) {
        float t = 0.f;
        #pragma unroll
        for (int i = 0; i < 8; i++) t += sm[i];
        rdeg = 1.0f / fmaxf(t, 1.0f);
    }
    __syncthreads();
    const float rd = rdeg;
    #pragma unroll
    for (int i = 0; i < 8; i++) {
        bf16 h, l;
        split2(v[i] * rd, h, l);
        size_t o = (size_t)row * Nn + tid + i * 256;
        g_adjh[o] = h; g_adjl[o] = l;
    }
}

__global__ void wtrans_all(const float* __restrict__ W2, const float* __restrict__ W1,
                           const float* __restrict__ Wr0, const float* __restrict__ Wo0,
                           const float* __restrict__ Wr1, const float* __restrict__ Wo1,
                           const float* __restrict__ Wr2, const float* __restrict__ Wo2)
{
    __shared__ float t[32][33];
    const int tb = blockIdx.x;
    const float* src; bf16* dh; bf16* dl; int R, C, tx, ty;
    if (tb < 192) {
        src = W2; dh = g_W2h; dl = g_W2l; R = LD_; C = Dd;
        ty = tb / 4; tx = tb % 4;
    } else if (tb < 384) {
        src = W1; dh = g_W1h; dl = g_W1l; R = Dd; C = LD_;
        int u = tb - 192; ty = u / 48; tx = u % 48;
    } else {
        int u = tb - 384; int l = u / 32; int v = u % 32;
        const float* wsrc[6] = {Wr0, Wo0, Wr1, Wo1, Wr2, Wo2};
        src = wsrc[l * 2 + (v < 16 ? 0 : 1)];
        if (v < 16) { dh = g_Wrh[l]; dl = g_Wrl[l]; }
        else        { dh = g_Woh[l]; dl = g_Wol[l]; }
        int w = v & 15; tx = w % 4; ty = w / 4; R = Dd; C = Dd;
    }
    const int c0 = tx * 32, r0 = ty * 32;
    const int x = threadIdx.x, y = threadIdx.y;
    #pragma unroll
    for (int i = 0; i < 32; i += 8)
        t[y + i][x] = src[(size_t)(r0 + y + i) * C + c0 + x];
    __syncthreads();
    #pragma unroll
    for (int i = 0; i < 32; i += 8) {
        bf16 h, l;
        split2(t[x][y + i], h, l);
        size_t o = (size_t)(c0 + y + i) * R + r0 + x;
        dh[o] = h; dl[o] = l;
    }
}

// ---------------- mlp2 reduce with coalesced transposed output -------------------
__global__ void reduce_wt(const float* __restrict__ p0, const float* __restrict__ p1,
                          const float* __restrict__ bias,
                          bf16* __restrict__ Ch, bf16* __restrict__ Cl,
                          bf16* __restrict__ Th, bf16* __restrict__ Tl)
{
    __shared__ float t[32][33];
    const int c0 = blockIdx.x * 32;
    const int r0 = blockIdx.y * 32;
    const int x = threadIdx.x, y = threadIdx.y;
    const float bcol = bias[c0 + x];
    #pragma unroll
    for (int i = 0; i < 32; i += 8) {
        const int row = r0 + y + i;
        const size_t o = (size_t)row * Dd + c0 + x;
        float v = p0[o] + p1[o] + bcol;
        t[y + i][x] = v;
        bf16 h, l; split2(v, h, l);
        Ch[o] = h; Cl[o] = l;
    }
    __syncthreads();
    const int bb = r0 >> 11;
    const size_t tbase = (size_t)bb * (Dd * (size_t)Nn) + (r0 & 2047) + x;
    #pragma unroll
    for (int i = 0; i < 32; i += 8) {
        const int col = c0 + y + i;
        bf16 h, l; split2(t[x][y + i], h, l);
        const size_t ot = tbase + (size_t)col * Nn;
        Th[ot] = h; Tl[ot] = l;
    }
}

// ---------------- bf16x2 tensor-core GEMM -------------------------------------
// R14 body (BK=64, 2 stages, AF32, smem-staged WT). NEW: PART4 — the dual
// GEMM's agg half sums 4 fp32 split-K partials in the A-loader (regs -> split
// -> STS), eliminating the reduce_k4 pass. Sum order matches reduce_k4.
#define STAGES 2
#define BM 64
#define BN 128
#define BK 64
#define KS2 72
#define OFF_AL (64 * KS2)
#define OFF_BH (2 * 64 * KS2)
#define OFF_BL (OFF_BH + 128 * KS2)
#define STAGE_H (OFF_BL + 128 * KS2)
#define GEMM_SMEM (STAGES * STAGE_H * 2)    // 110592 B
#define TS 72

template<bool DUAL, bool RELU, bool BIAS, bool WF32, bool WSPL, bool WT,
         bool SPLITK, bool AF32, bool PART4>
__global__ void __launch_bounds__(256, 2)
gemm_bf(const bf16* __restrict__ Ah, const bf16* __restrict__ Al,
        const float* __restrict__ Af,
        const bf16* __restrict__ Bh, const bf16* __restrict__ Bl,
        const bf16* __restrict__ A2h, const bf16* __restrict__ A2l,
        const bf16* __restrict__ B2h, const bf16* __restrict__ B2l,
        const float* __restrict__ bias,
        float* __restrict__ Cf, bf16* __restrict__ Ch, bf16* __restrict__ Cl,
        bf16* __restrict__ Th, bf16* __restrict__ Tl,
        int N, int ldK, int kLen, int zmask, int zshift,
        size_t sA, size_t sB, size_t sC, size_t sPart)
{
    extern __shared__ bf16 smem[];
    const uint32_t sbase = smem_u32(smem);
    const int tid = threadIdx.x;
    const int lane = tid & 31, wid = tid >> 5;
    const int warpM = wid & 1, warpN = wid >> 1;
    const int gid = lane >> 2, tg = lane & 3;

    const int m0 = blockIdx.y * BM, n0 = blockIdx.x * BN;
    int batch, split, kOff;
    if (SPLITK) { batch = blockIdx.z & zmask; split = blockIdx.z >> zshift;
                  kOff = split * kLen; }
    else        { batch = blockIdx.z; split = 0; kOff = 0; }

    const bf16* pAh = Ah + (size_t)batch * sA;
    const bf16* pAl = Al + (size_t)batch * sA;
    const bf16* pBh = Bh + (size_t)batch * sB;
    const bf16* pBl = Bl + (size_t)batch * sB;

    const int nk1 = kLen / BK;
    const int nk  = DUAL ? 2 * nk1 : nk1;

    auto issue = [&](int tile, int s) {
        const bf16 *bh, *bl; int k0;
        bool second = DUAL && (tile >= nk1);
        if (second) { bh = B2h; bl = B2l; k0 = (tile - nk1) * BK; }
        else        { bh = pBh; bl = pBl; k0 = kOff + tile * BK; }
        const uint32_t st = sbase + s * (STAGE_H * 2);

        // ---- A side ----
        if ((AF32 || PART4) && !second) {
            char* sp = reinterpret_cast<char*>(smem) + s * (STAGE_H * 2);
            #pragma unroll
            for (int i = 0; i < 2; i++) {
                int idx = tid + i * 256;
                int row = idx >> 3, c = idx & 7;
                size_t g = (size_t)(m0 + row) * ldK + k0 + c * 8;
                float v[8];
                if (PART4) {
                    const float* q0 = Af + g;
                    const float* q1 = Af + sPart + g;
                    const float* q2 = Af + 2 * sPart + g;
                    const float* q3 = Af + 3 * sPart + g;
                    float4 a0 = *reinterpret_cast<const float4*>(q0);
                    float4 a1 = *reinterpret_cast<const float4*>(q0 + 4);
                    float4 b0 = *reinterpret_cast<const float4*>(q1);
                    float4 b1 = *reinterpret_cast<const float4*>(q1 + 4);
                    float4 c0_ = *reinterpret_cast<const float4*>(q2);
                    float4 c1 = *reinterpret_cast<const float4*>(q2 + 4);
                    float4 d0 = *reinterpret_cast<const float4*>(q3);
                    float4 d1 = *reinterpret_cast<const float4*>(q3 + 4);
                    v[0] = (a0.x + b0.x) + (c0_.x + d0.x);
                    v[1] = (a0.y + b0.y) + (c0_.y + d0.y);
                    v[2] = (a0.z + b0.z) + (c0_.z + d0.z);
                    v[3] = (a0.w + b0.w) + (c0_.w + d0.w);
                    v[4] = (a1.x + b1.x) + (c1.x + d1.x);
                    v[5] = (a1.y + b1.y) + (c1.y + d1.y);
                    v[6] = (a1.z + b1.z) + (c1.z + d1.z);
                    v[7] = (a1.w + b1.w) + (c1.w + d1.w);
                } else {
                    float4 u0 = *reinterpret_cast<const float4*>(Af + g);
                    float4 u1 = *reinterpret_cast<const float4*>(Af + g + 4);
                    v[0] = u0.x; v[1] = u0.y; v[2] = u0.z; v[3] = u0.w;
                    v[4] = u1.x; v[5] = u1.y; v[6] = u1.z; v[7] = u1.w;
                }
                __nv_bfloat162 hh[4], ll[4];
                #pragma unroll
                for (int j = 0; j < 4; j++) {
                    bf16 h0_, l0_, h1_, l1_;
                    split2(v[2 * j], h0_, l0_); split2(v[2 * j + 1], h1_, l1_);
                    hh[j] = __nv_bfloat162(h0_, h1_); ll[j] = __nv_bfloat162(l0_, l1_);
                }
                uint32_t dof = (uint32_t)(row * KS2 + c * 8) * 2;
                *reinterpret_cast<uint4*>(sp + dof) = *reinterpret_cast<uint4*>(hh);
                *reinterpret_cast<uint4*>(sp + OFF_AL * 2 + dof) = *reinterpret_cast<uint4*>(ll);
            }
        } else {
            const bf16 *ah, *al;
            if (second) { ah = A2h; al = A2l; }
            else        { ah = pAh; al = pAl; }
            #pragma unroll
            for (int i = 0; i < 2; i++) {
                int idx = tid + i * 256;
                int row = idx >> 3, c = idx & 7;
                uint32_t dof = (uint32_t)(row * KS2 + c * 8) * 2;
                size_t gof = (size_t)(m0 + row) * ldK + k0 + c * 8;
                cp_async16(st + dof,              ah + gof);
                cp_async16(st + OFF_AL * 2 + dof, al + gof);
            }
        }
        // ---- B side ----
        #pragma unroll
        for (int i = 0; i < 4; i++) {
            int idx = tid + i * 256;
            int row = idx >> 3, c = idx & 7;
            uint32_t dof = (uint32_t)(row * KS2 + c * 8) * 2;
            size_t gof = (size_t)(n0 + row) * ldK + k0 + c * 8;
            cp_async16(st + OFF_BH * 2 + dof, bh + gof);
            cp_async16(st + OFF_BL * 2 + dof, bl + gof);
        }
        cp_commit();
    };

    float acc[2][4][4];
    #pragma unroll
    for (int mi = 0; mi < 2; mi++)
        #pragma unroll
        for (int ni = 0; ni < 4; ni++)
            #pragma unroll
            for (int j = 0; j < 4; j++) acc[mi][ni][j] = 0.f;

    const int ar = lane & 15, ak = (lane >> 4) * 8;
    const uint32_t a_off = (uint32_t)((warpM * 32 + ar) * KS2 + ak) * 2;
    const int nr = (lane & 7) + ((lane >> 4) * 8);
    const int bk = ((lane >> 3) & 1) * 8;
    const uint32_t b_off = (uint32_t)((warpN * 32 + nr) * KS2 + bk) * 2;

    #pragma unroll
    for (int s = 0; s < STAGES - 1; s++) issue(s, s);

    for (int kt = 0; kt < nk; ++kt) {
        cp_wait<STAGES - 2>();
        __syncthreads();
        if (kt + STAGES - 1 < nk) issue(kt + STAGES - 1, (kt + STAGES - 1) % STAGES);

        const uint32_t st = sbase + (kt % STAGES) * (STAGE_H * 2);
        const uint32_t aA = st + a_off;
        const uint32_t aB = st + OFF_BH * 2 + b_off;

        #pragma unroll
        for (int ks = 0; ks < 4; ks++) {
            const uint32_t ko = ks * 32;
            uint32_t ah_[2][4], al_[2][4], bh_[2][4], bl_[2][4];
            #pragma unroll
            for (int mi = 0; mi < 2; mi++) {
                ldmx4(ah_[mi], aA + mi * (16 * KS2 * 2) + ko);
                ldmx4(al_[mi], aA + OFF_AL * 2 + mi * (16 * KS2 * 2) + ko);
            }
            #pragma unroll
            for (int np = 0; np < 2; np++) {
                ldmx4(bh_[np], aB + np * (16 * KS2 * 2) + ko);
                ldmx4(bl_[np], aB + (OFF_BL - OFF_BH) * 2 + np * (16 * KS2 * 2) + ko);
            }
            #pragma unroll
            for (int mi = 0; mi < 2; mi++)
                #pragma unroll
                for (int ni = 0; ni < 4; ni++) {
                    const int np = ni >> 1, jo = (ni & 1) * 2;
                    mma_bf16(acc[mi][ni], ah_[mi], &bh_[np][jo]);
                    mma_bf16(acc[mi][ni], ah_[mi], &bl_[np][jo]);
                    mma_bf16(acc[mi][ni], al_[mi], &bh_[np][jo]);
                }
        }
    }
    cp_wait<0>();
    bf16* thbuf = smem;
    bf16* tlbuf = smem + 128 * TS;
    if (WT) __syncthreads();

    // epilogue
    const size_t obase = (SPLITK ? (size_t)split * sPart : 0) + (size_t)batch * sC;
    #pragma unroll
    for (int mi = 0; mi < 2; mi++) {
        const int rl = warpM * 32 + mi * 16 + gid;
        #pragma unroll
        for (int ni = 0; ni < 4; ni++) {
            const int cl = warpN * 32 + ni * 8 + 2 * tg;
            const int col = n0 + cl;
            float* c = acc[mi][ni];
            float b0 = 0.f, b1 = 0.f;
            if (BIAS) { b0 = bias[col]; b1 = bias[col + 1]; }
            #pragma unroll
            for (int h2 = 0; h2 < 2; h2++) {
                const int row = m0 + rl + 8 * h2;
                float v0 = c[2 * h2 + 0] + b0;
                float v1 = c[2 * h2 + 1] + b1;
                if (RELU) { v0 = fmaxf(v0, 0.f); v1 = fmaxf(v1, 0.f); }
                const size_t o = obase + (size_t)row * N + col;
                if (SPLITK || WF32)
                    *reinterpret_cast<float2*>(Cf + o) = make_float2(v0, v1);
                if (WSPL || WT) {
                    bf16 h0_, l0_, h1_, l1_;
                    split2(v0, h0_, l0_); split2(v1, h1_, l1_);
                    if (WSPL) {
                        *reinterpret_cast<__nv_bfloat162*>(Ch + o) = __nv_bfloat162(h0_, h1_);
                        *reinterpret_cast<__nv_bfloat162*>(Cl + o) = __nv_bfloat162(l0_, l1_);
                    }
                    if (WT) {
                        const int r2 = rl + 8 * h2;
                        thbuf[cl * TS + r2] = h0_;       tlbuf[cl * TS + r2] = l0_;
                        thbuf[(cl + 1) * TS + r2] = h1_; tlbuf[(cl + 1) * TS + r2] = l1_;
                    }
                }
            }
        }
    }
    if (WT) {
        __syncthreads();
        const int bb_ = m0 >> 11;
        const size_t tb = (size_t)bb_ * (Dd * (size_t)Nn) + (m0 & 2047);
        #pragma unroll
        for (int it = 0; it < 4; it++) {
            const int idx = tid + it * 256;
            const int colr = idx >> 3, ch = idx & 7;
            uint4 vh = *reinterpret_cast<uint4*>(thbuf + colr * TS + ch * 8);
            uint4 vl = *reinterpret_cast<uint4*>(tlbuf + colr * TS + ch * 8);
            const size_t ot = tb + (size_t)(n0 + colr) * Nn + ch * 8;
            *reinterpret_cast<uint4*>(Th + ot) = vh;
            *reinterpret_cast<uint4*>(Tl + ot) = vl;
        }
    }
}

// ---------------- launch --------------------------------------------------------
extern "C" void kernel_launch(void* const* d_in, const int* in_sizes, int n_in,
                              void* d_out, int out_size)
{
    (void)in_sizes; (void)n_in; (void)out_size;
    const float* x      = (const float*)d_in[0];
    const float* adj    = (const float*)d_in[1];
    const float* W_mlp2 = (const float*)d_in[2];
    const float* b_mlp2 = (const float*)d_in[3];
    const float* Wr[3]  = {(const float*)d_in[4], (const float*)d_in[7], (const float*)d_in[10]};
    const float* Wo[3]  = {(const float*)d_in[5], (const float*)d_in[8], (const float*)d_in[11]};
    const float* bs[3]  = {(const float*)d_in[6], (const float*)d_in[9], (const float*)d_in[12]};
    const float* W_mlp1 = (const float*)d_in[13];
    const float* b_mlp1 = (const float*)d_in[14];
    float* out = (float*)d_out;

    bf16 *h0h, *h0l, *h1h, *h1l, *hTh, *hTl;
    bf16 *W2h, *W2l, *W1h, *W1l, *Wrh, *Wrl, *Woh, *Wol, *adjh, *adjl;
    float* part;
    cudaGetSymbolAddress((void**)&h0h,  g_h0h); cudaGetSymbolAddress((void**)&h0l, g_h0l);
    cudaGetSymbolAddress((void**)&h1h,  g_h1h); cudaGetSymbolAddress((void**)&h1l, g_h1l);
    cudaGetSymbolAddress((void**)&hTh,  g_hTh); cudaGetSymbolAddress((void**)&hTl, g_hTl);
    cudaGetSymbolAddress((void**)&W2h,  g_W2h); cudaGetSymbolAddress((void**)&W2l, g_W2l);
    cudaGetSymbolAddress((void**)&W1h,  g_W1h); cudaGetSymbolAddress((void**)&W1l, g_W1l);
    cudaGetSymbolAddress((void**)&Wrh,  g_Wrh); cudaGetSymbolAddress((void**)&Wrl, g_Wrl);
    cudaGetSymbolAddress((void**)&Woh,  g_Woh); cudaGetSymbolAddress((void**)&Wol, g_Wol);
    cudaGetSymbolAddress((void**)&adjh, g_adjh); cudaGetSymbolAddress((void**)&adjl, g_adjl);
    cudaGetSymbolAddress((void**)&part, g_part);
    const size_t sPart = (size_t)MT * Dd;
    float *p0 = part, *p1 = part + sPart;

    cudaFuncSetAttribute(gemm_bf<false, false, false, false, false, false, true,  true,  false>,
                         cudaFuncAttributeMaxDynamicSharedMemorySize, GEMM_SMEM);
    cudaFuncSetAttribute(gemm_bf<false, false, false, false, false, false, true,  false, false>,
                         cudaFuncAttributeMaxDynamicSharedMemorySize, GEMM_SMEM);
    cudaFuncSetAttribute(gemm_bf<true,  true,  true,  false, true,  true,  false, false, true >,
                         cudaFuncAttributeMaxDynamicSharedMemorySize, GEMM_SMEM);
    cudaFuncSetAttribute(gemm_bf<true,  false, true,  false, true,  false, false, false, true >,
                         cudaFuncAttributeMaxDynamicSharedMemorySize, GEMM_SMEM);
    cudaFuncSetAttribute(gemm_bf<false, false, true,  true,  false, false, false, false, false>,
                         cudaFuncAttributeMaxDynamicSharedMemorySize, GEMM_SMEM);

    const size_t sHD = (size_t)Nn * Dd;

    // preprocessing
    adj_fused<<<Nn, 256>>>(adj);
    wtrans_all<<<480, dim3(32, 8)>>>(W_mlp2, W_mlp1, Wr[0], Wo[0], Wr[1], Wo[1], Wr[2], Wo[2]);

    // mlp2 split-K 2 (AF32 loader reads x fp32 directly): grid 256
    gemm_bf<false, false, false, false, false, false, true, true, false>
        <<<dim3(Dd / BN, MT / BM, 2), 256, GEMM_SMEM>>>(
        nullptr, nullptr, x, W2h, W2l, nullptr, nullptr, nullptr, nullptr,
        nullptr, part, nullptr, nullptr, nullptr, nullptr,
        Dd, LD_, LD_ / 2, 0, 0, 0, 0, 0, sPart);
    reduce_wt<<<dim3(Dd / 32, MT / 32), dim3(32, 8)>>>(
        p0, p1, b_mlp2, h0h, h0l, hTh, hTl);

    bf16* hinh = h0h; bf16* hinl = h0l;
    bf16* houth = h1h; bf16* houtl = h1l;
    for (int l = 0; l < 3; l++) {
        // agg partials = adjn @ hin (split-K 4 per batch; grid 512)
        gemm_bf<false, false, false, false, false, false, true, false, false>
            <<<dim3(Dd / BN, Nn / BM, Bb * 4), 256, GEMM_SMEM>>>(
            adjh, adjl, nullptr, hTh, hTl, nullptr, nullptr, nullptr, nullptr,
            nullptr, part, nullptr, nullptr, nullptr, nullptr,
            Dd, Nn, Nn / 4, 3, 2, 0, sHD, sHD, sPart);
        // h' = act((p0+p1+p2+p3)@Wr + hin@Wo + b): PART4 loader, grid 128
        if (l < 2)
            gemm_bf<true, true, true, false, true, true, false, false, true>
                <<<dim3(Dd / BN, MT / BM, 1), 256, GEMM_SMEM>>>(
                nullptr, nullptr, part, Wrh + l * Dd * Dd, Wrl + l * Dd * Dd,
                hinh, hinl, Woh + l * Dd * Dd, Wol + l * Dd * Dd,
                bs[l], nullptr, houth, houtl, hTh, hTl,
                Dd, Dd, Dd, 0, 0, 0, 0, 0, sPart);
        else
            gemm_bf<true, false, true, false, true, false, false, false, true>
                <<<dim3(Dd / BN, MT / BM, 1), 256, GEMM_SMEM>>>(
                nullptr, nullptr, part, Wrh + l * Dd * Dd, Wrl + l * Dd * Dd,
                hinh, hinl, Woh + l * Dd * Dd, Wol + l * Dd * Dd,
                bs[l], nullptr, houth, houtl, nullptr, nullptr,
                Dd, Dd, Dd, 0, 0, 0, 0, 0, sPart);
        { bf16* t = hinh; hinh = houth; houth = t; }
        { bf16* t = hinl; hinl = houtl; houtl = t; }
    }

    // mlp1: out = hin @ W_mlp1 + b   (grid 1536)
    gemm_bf<false, false, true, true, false, false, false, false, false>
        <<<dim3(LD_ / BN, MT / BM, 1), 256, GEMM_SMEM>>>(
        hinh, hinl, nullptr, W1h, W1l, nullptr, nullptr, nullptr, nullptr,
        b_mlp1, out, nullptr, nullptr, nullptr, nullptr,
        LD_, Dd, Dd, 0, 0, 0, 0, 0, 0);
}